// round 10
// baseline (speedup 1.0000x reference)
#include <cuda_runtime.h>

#define DIMC 256
#define RESV 256
#define H2 128
#define HEADS 8
#define HD 32
#define NPIX 64
#define NWIN 512
#define PIXTOT (NWIN * NPIX)   // 32768
#define ATTN_SCALE 0.17677669529663687f
#define SROW 68                // padded smem row stride (floats)
#define PSROW 132              // proj smem row stride (floats), 128-wide tiles

typedef unsigned long long ull;

// ---- packed fp32x2 helpers (FFMA2 — only reachable via PTX fma.rn.f32x2) ----
__device__ __forceinline__ void ffma2(ull& d, ull a, ull b) {
    asm("fma.rn.f32x2 %0, %1, %2, %0;" : "+l"(d) : "l"(a), "l"(b));
}
__device__ __forceinline__ ull pack2(float lo, float hi) {
    ull r; asm("mov.b64 %0, {%1, %2};" : "=l"(r) : "f"(lo), "f"(hi)); return r;
}
__device__ __forceinline__ float2 unpack2(ull v) {
    float2 r; asm("mov.b64 {%0, %1}, %2;" : "=f"(r.x), "=f"(r.y) : "l"(v)); return r;
}

// ---------------- scratch (static device allocations; no cudaMalloc) -------
__device__ float g_ll[2 * DIMC * H2 * H2];
__device__ float g_lh[2 * DIMC * H2 * H2];
__device__ float g_hl[2 * DIMC * H2 * H2];
__device__ float g_hh[2 * DIMC * H2 * H2];
__device__ float g_attn[NWIN * HEADS * NPIX * NPIX]; // softmax'd attn, [wh][m][n]
__device__ float g_att[DIMC * PIXTOT];    // relu(attention out), [c][pix]
__device__ float g_proj[DIMC * PIXTOT];   // proj out, [o][pix]
__device__ float g_bias[HEADS * NPIX * NPIX];

// ---------------- K0: expand attention bias table ---------------------------
__global__ void bias_kernel(const float* __restrict__ ab, const int* __restrict__ bidx) {
    int i = blockIdx.x * 256 + threadIdx.x;     // 32768 total
    int h = i >> 12;
    g_bias[i] = ab[h * 64 + bidx[i & 4095]];
}

// ---------------- K1: wavelet transform (depthwise 2x2 stride 2) -----------
__global__ void wt_kernel(const float* __restrict__ x, const float* __restrict__ wt) {
    int xo = threadIdx.x;          // 0..127
    int y  = blockIdx.x;           // 0..127
    int bc = blockIdx.y;           // 0..511 (b*256 + c)
    int c  = bc & 255;

    const float4 f0 = __ldg((const float4*)&wt[(4 * c + 0) * 4]);
    const float4 f1 = __ldg((const float4*)&wt[(4 * c + 1) * 4]);
    const float4 f2 = __ldg((const float4*)&wt[(4 * c + 2) * 4]);
    const float4 f3 = __ldg((const float4*)&wt[(4 * c + 3) * 4]);

    int ib = (bc * RESV + 2 * y) * RESV + 2 * xo;
    float2 p0 = *(const float2*)&x[ib];
    float2 p1 = *(const float2*)&x[ib + RESV];

    int ob = (bc * H2 + y) * H2 + xo;
    g_ll[ob] = p0.x * f0.x + p0.y * f0.y + p1.x * f0.z + p1.y * f0.w;
    g_lh[ob] = p0.x * f1.x + p0.y * f1.y + p1.x * f1.z + p1.y * f1.w;
    g_hl[ob] = p0.x * f2.x + p0.y * f2.y + p1.x * f2.z + p1.y * f2.w;
    g_hh[ob] = p0.x * f3.x + p0.y * f3.y + p1.x * f3.z + p1.y * f3.w;
}

// ---------------- K2a: attention matrices (all heads parallel) --------------
__global__ __launch_bounds__(256) void attn_mat_kernel(
    const float* __restrict__ dww, const float* __restrict__ dwb) {
    __shared__ float lh_s[HD * SROW];
    __shared__ float k_s[HD * SROW];
    __shared__ float q_s[HD * SROW];
    __shared__ float w_s[HD * 25];

    const int t  = threadIdx.x;
    const int wh = blockIdx.x;           // 0..4095
    const int w  = wh >> 3;
    const int h  = wh & 7;
    const int b  = w >> 8;
    const int wy = (w >> 4) & 15;
    const int wx = w & 15;
    const int dl = t >> 3;               // 0..31
    const int py = t & 7;                // 0..7

    {
        int ch   = b * DIMC + h * HD + dl;
        int base = (ch * H2 + wy * 8 + py) * H2 + wx * 8;
        int o0   = dl * SROW + py * 8;
        *(float4*)&lh_s[o0]     = *(const float4*)&g_lh[base];
        *(float4*)&lh_s[o0 + 4] = *(const float4*)&g_lh[base + 4];
        *(float4*)&k_s[o0]      = *(const float4*)&g_hl[base];
        *(float4*)&k_s[o0 + 4]  = *(const float4*)&g_hl[base + 4];
    }
    for (int i = t; i < HD * 25; i += 256) w_s[i] = dww[h * HD * 25 + i];
    __syncthreads();

    // ---- q = depthwise 5x5 conv on lh ----
    {
        float accq[8];
        float bias0 = __ldg(&dwb[h * HD + dl]);
        #pragma unroll
        for (int px = 0; px < 8; ++px) accq[px] = bias0;
        #pragma unroll
        for (int u = 0; u < 5; ++u) {
            int yy = py + u - 2;
            if (yy >= 0 && yy < 8) {
                float4 r0 = *(const float4*)&lh_s[dl * SROW + yy * 8];
                float4 r1 = *(const float4*)&lh_s[dl * SROW + yy * 8 + 4];
                float r[8] = {r0.x, r0.y, r0.z, r0.w, r1.x, r1.y, r1.z, r1.w};
                #pragma unroll
                for (int v = 0; v < 5; ++v) {
                    float wv = w_s[dl * 25 + u * 5 + v];
                    #pragma unroll
                    for (int px = 0; px < 8; ++px) {
                        int xx = px + v - 2;
                        if (xx >= 0 && xx < 8)
                            accq[px] += r[xx] * wv;
                    }
                }
            }
        }
        #pragma unroll
        for (int px = 0; px < 8; ++px) q_s[dl * SROW + py * 8 + px] = accq[px];
    }
    __syncthreads();

    // ---- attn = softmax(q.k * scale + bias), packed f32x2 QK ----
    {
        int n  = t >> 2;
        int mq = t & 3;
        ull acc2[8];
        #pragma unroll
        for (int i = 0; i < 8; ++i) acc2[i] = 0ull;

        #pragma unroll 4
        for (int d2 = 0; d2 < HD; ++d2) {
            float qd = q_s[d2 * SROW + n];
            ull pq = pack2(qd, qd);
            const float* kp = &k_s[d2 * SROW + mq * 16];
            ulonglong2 k01 = *(const ulonglong2*)(kp);
            ulonglong2 k23 = *(const ulonglong2*)(kp + 4);
            ulonglong2 k45 = *(const ulonglong2*)(kp + 8);
            ulonglong2 k67 = *(const ulonglong2*)(kp + 12);
            ffma2(acc2[0], pq, k01.x);
            ffma2(acc2[1], pq, k01.y);
            ffma2(acc2[2], pq, k23.x);
            ffma2(acc2[3], pq, k23.y);
            ffma2(acc2[4], pq, k45.x);
            ffma2(acc2[5], pq, k45.y);
            ffma2(acc2[6], pq, k67.x);
            ffma2(acc2[7], pq, k67.y);
        }

        float acc[16];
        #pragma unroll
        for (int i = 0; i < 8; ++i) {
            float2 u = unpack2(acc2[i]);
            acc[2 * i]     = u.x;
            acc[2 * i + 1] = u.y;
        }

        const float* bptr = &g_bias[h * 4096 + n * 64 + mq * 16];
        float mx = -1e30f;
        #pragma unroll
        for (int mi = 0; mi < 16; ++mi) {
            acc[mi] = acc[mi] * ATTN_SCALE + __ldg(&bptr[mi]);
            mx = fmaxf(mx, acc[mi]);
        }
        mx = fmaxf(mx, __shfl_xor_sync(0xffffffffu, mx, 1));
        mx = fmaxf(mx, __shfl_xor_sync(0xffffffffu, mx, 2));
        float s = 0.f;
        #pragma unroll
        for (int mi = 0; mi < 16; ++mi) {
            float e = __expf(acc[mi] - mx);
            acc[mi] = e;
            s += e;
        }
        s += __shfl_xor_sync(0xffffffffu, s, 1);
        s += __shfl_xor_sync(0xffffffffu, s, 2);
        float inv = 1.f / s;

        float* op = &g_attn[wh * 4096];
        #pragma unroll
        for (int mi = 0; mi < 16; ++mi)
            op[(mq * 16 + mi) * 64 + n] = acc[mi] * inv;   // [m][n]
    }
}

// ---------------- K2b: sequential AV chain, 2 CTAs per window (d-split) ----
// Double-buffered attn tile -> ONE __syncthreads per head; v/o are
// warp-private (each warp owns local d rows 4wp..4wp+3), so v-build,
// relu-store and the FMA chain never cross warps (__syncwarp only).
__global__ __launch_bounds__(128) void attn_av_kernel() {
    __shared__ float attn_sd[2 * NPIX * NPIX];  // 2 x 16KB
    __shared__ float v_s[16 * NPIX];            // 4KB
    __shared__ float o_s[16 * NPIX];            // 4KB

    const int t    = threadIdx.x;               // 0..127
    const int wc   = blockIdx.x;                // 0..1023
    const int w    = wc >> 1;
    const int dbase = (wc & 1) * 16;
    const int b  = w >> 8;
    const int wy = (w >> 4) & 15;
    const int wx = w & 15;
    const int wp   = t >> 5;                    // warp 0..3 -> rows 4wp..4wp+3
    const int lane = t & 31;

    // warp-private row mapping for v/o/ll/g_att
    const int r   = 4 * wp + (lane >> 3);       // local d row 0..15
    const int py  = lane & 7;                   // m = py*8 + px
    const int vbase = r * 64 + py * 8;

    float4 pa[8];   // prefetched attn tile (staged via c-layout)
    float4 pl[2];   // prefetched ll row chunk (warp-private mapping)

    {
        const float* ap = &g_attn[(w * 8 + 0) * 4096];
        #pragma unroll
        for (int i = 0; i < 8; ++i)
            pa[i] = *(const float4*)&ap[(t + 128 * i) * 4];
        int ch = b * DIMC + 0 * HD + dbase + r;
        const float* lp = &g_ll[(ch * H2 + wy * 8 + py) * H2 + wx * 8];
        pl[0] = *(const float4*)lp;
        pl[1] = *(const float4*)(lp + 4);
    }

    for (int h = 0; h < HEADS; ++h) {
        float* buf = &attn_sd[(h & 1) * 4096];

        // ---- stage attn tile into current buffer ----
        #pragma unroll
        for (int i = 0; i < 8; ++i)
            *(float4*)&buf[(t + 128 * i) * 4] = pa[i];

        // ---- warp-private: v = ll (+ prev o), relu-store prev o ----
        {
            float4 v0 = pl[0], v1 = pl[1];
            if (h > 0) {
                float4 o0 = *(const float4*)&o_s[vbase];
                float4 o1 = *(const float4*)&o_s[vbase + 4];
                v0.x += o0.x; v0.y += o0.y; v0.z += o0.z; v0.w += o0.w;
                v1.x += o1.x; v1.y += o1.y; v1.z += o1.z; v1.w += o1.w;
                float* gp = &g_att[((h - 1) * HD + dbase + r) * PIXTOT + w * 64 + py * 8];
                *(float4*)gp = make_float4(fmaxf(o0.x, 0.f), fmaxf(o0.y, 0.f),
                                           fmaxf(o0.z, 0.f), fmaxf(o0.w, 0.f));
                *(float4*)(gp + 4) = make_float4(fmaxf(o1.x, 0.f), fmaxf(o1.y, 0.f),
                                                 fmaxf(o1.z, 0.f), fmaxf(o1.w, 0.f));
            }
            *(float4*)&v_s[vbase]     = v0;
            *(float4*)&v_s[vbase + 4] = v1;
        }

        // ---- prefetch next head ----
        if (h < HEADS - 1) {
            const float* ap = &g_attn[(w * 8 + h + 1) * 4096];
            #pragma unroll
            for (int i = 0; i < 8; ++i)
                pa[i] = *(const float4*)&ap[(t + 128 * i) * 4];
            int ch = b * DIMC + (h + 1) * HD + dbase + r;
            const float* lp = &g_ll[(ch * H2 + wy * 8 + py) * H2 + wx * 8];
            pl[0] = *(const float4*)lp;
            pl[1] = *(const float4*)(lp + 4);
        }

        __syncthreads();   // the ONLY cta barrier per head: staging complete

        // ---- out[d][n] = sum_m v[d][m] * attn_t[m][n] (own-warp rows) ----
        ull acc2[4][2];
        #pragma unroll
        for (int j = 0; j < 4; ++j) { acc2[j][0] = 0ull; acc2[j][1] = 0ull; }

        #pragma unroll
        for (int m = 0; m < 64; m += 4) {
            ulonglong2 va0 = *(const ulonglong2*)&v_s[(4 * wp + 0) * 64 + m];
            ulonglong2 va1 = *(const ulonglong2*)&v_s[(4 * wp + 1) * 64 + m];
            ulonglong2 va2 = *(const ulonglong2*)&v_s[(4 * wp + 2) * 64 + m];
            ulonglong2 va3 = *(const ulonglong2*)&v_s[(4 * wp + 3) * 64 + m];
            float b0l = buf[(m + 0) * 64 + lane];
            float b1l = buf[(m + 1) * 64 + lane];
            float b2l = buf[(m + 2) * 64 + lane];
            float b3l = buf[(m + 3) * 64 + lane];
            float b0h = buf[(m + 0) * 64 + lane + 32];
            float b1h = buf[(m + 1) * 64 + lane + 32];
            float b2h = buf[(m + 2) * 64 + lane + 32];
            float b3h = buf[(m + 3) * 64 + lane + 32];
            ull bl01 = pack2(b0l, b1l), bl23 = pack2(b2l, b3l);
            ull bh01 = pack2(b0h, b1h), bh23 = pack2(b2h, b3h);
            ffma2(acc2[0][0], va0.x, bl01); ffma2(acc2[0][0], va0.y, bl23);
            ffma2(acc2[1][0], va1.x, bl01); ffma2(acc2[1][0], va1.y, bl23);
            ffma2(acc2[2][0], va2.x, bl01); ffma2(acc2[2][0], va2.y, bl23);
            ffma2(acc2[3][0], va3.x, bl01); ffma2(acc2[3][0], va3.y, bl23);
            ffma2(acc2[0][1], va0.x, bh01); ffma2(acc2[0][1], va0.y, bh23);
            ffma2(acc2[1][1], va1.x, bh01); ffma2(acc2[1][1], va1.y, bh23);
            ffma2(acc2[2][1], va2.x, bh01); ffma2(acc2[2][1], va2.y, bh23);
            ffma2(acc2[3][1], va3.x, bh01); ffma2(acc2[3][1], va3.y, bh23);
        }
        #pragma unroll
        for (int j = 0; j < 4; ++j) {
            float2 u0 = unpack2(acc2[j][0]);
            float2 u1 = unpack2(acc2[j][1]);
            o_s[(4 * wp + j) * 64 + lane]      = u0.x + u0.y;
            o_s[(4 * wp + j) * 64 + lane + 32] = u1.x + u1.y;
        }
        __syncwarp();   // own-warp o_s visible for next head's v-build
    }

    // ---- epilogue: relu-store head 7 (warp-private) ----
    {
        float4 o0 = *(const float4*)&o_s[vbase];
        float4 o1 = *(const float4*)&o_s[vbase + 4];
        float* gp = &g_att[(7 * HD + dbase + r) * PIXTOT + w * 64 + py * 8];
        *(float4*)gp = make_float4(fmaxf(o0.x, 0.f), fmaxf(o0.y, 0.f),
                                   fmaxf(o0.z, 0.f), fmaxf(o0.w, 0.f));
        *(float4*)(gp + 4) = make_float4(fmaxf(o1.x, 0.f), fmaxf(o1.y, 0.f),
                                         fmaxf(o1.z, 0.f), fmaxf(o1.w, 0.f));
    }
}

// ---------------- K3: proj GEMM  C[256,32768] = W[256,256] @ A + bias ------
// 128x128 tile, 8x8 micro-tile (packed f32x2), double-buffered smem:
// ONE __syncthreads per k-tile, warp skew allowed.
__global__ __launch_bounds__(256) void proj_gemm(
    const float* __restrict__ Wm, const float* __restrict__ pb) {
    __shared__ float As[2][16 * PSROW];
    __shared__ float Bs[2][16 * PSROW];

    const int t  = threadIdx.x;
    const int n0 = blockIdx.x * 128;
    const int m0 = blockIdx.y * 128;
    const int tx = t & 15, ty = t >> 4;

    const int am = t >> 1;
    const int ak = (t & 1) * 8;
    const int bk = t >> 4;
    const int bn = (t & 15) * 8;

    ull acc2[8][4];
    #pragma unroll
    for (int i = 0; i < 8; ++i)
        #pragma unroll
        for (int j = 0; j < 4; ++j) acc2[i][j] = 0ull;

    float4 pa0 = *(const float4*)&Wm[(m0 + am) * 256 + ak];
    float4 pa1 = *(const float4*)&Wm[(m0 + am) * 256 + ak + 4];
    float4 pb0 = *(const float4*)&g_att[bk * PIXTOT + n0 + bn];
    float4 pb1 = *(const float4*)&g_att[bk * PIXTOT + n0 + bn + 4];

    for (int kt = 0; kt < 16; ++kt) {
        float* as = As[kt & 1];
        float* bs = Bs[kt & 1];
        as[(ak + 0) * PSROW + am] = pa0.x;
        as[(ak + 1) * PSROW + am] = pa0.y;
        as[(ak + 2) * PSROW + am] = pa0.z;
        as[(ak + 3) * PSROW + am] = pa0.w;
        as[(ak + 4) * PSROW + am] = pa1.x;
        as[(ak + 5) * PSROW + am] = pa1.y;
        as[(ak + 6) * PSROW + am] = pa1.z;
        as[(ak + 7) * PSROW + am] = pa1.w;
        *(float4*)&bs[bk * PSROW + bn]     = pb0;
        *(float4*)&bs[bk * PSROW + bn + 4] = pb1;

        if (kt < 15) {
            int k0 = (kt + 1) * 16;
            pa0 = *(const float4*)&Wm[(m0 + am) * 256 + k0 + ak];
            pa1 = *(const float4*)&Wm[(m0 + am) * 256 + k0 + ak + 4];
            pb0 = *(const float4*)&g_att[(k0 + bk) * PIXTOT + n0 + bn];
            pb1 = *(const float4*)&g_att[(k0 + bk) * PIXTOT + n0 + bn + 4];
        }
        __syncthreads();   // staging of buf[kt&1] complete

        #pragma unroll
        for (int k = 0; k < 16; ++k) {
            float4 a0 = *(const float4*)&as[k * PSROW + ty * 4];
            float4 a1 = *(const float4*)&as[k * PSROW + 64 + ty * 4];
            ulonglong2 b01 = *(const ulonglong2*)&bs[k * PSROW + tx * 4];
            ulonglong2 b23 = *(const ulonglong2*)&bs[k * PSROW + 64 + tx * 4];
            float av[8] = {a0.x, a0.y, a0.z, a0.w, a1.x, a1.y, a1.z, a1.w};
            #pragma unroll
            for (int i = 0; i < 8; ++i) {
                ull pav = pack2(av[i], av[i]);
                ffma2(acc2[i][0], pav, b01.x);
                ffma2(acc2[i][1], pav, b01.y);
                ffma2(acc2[i][2], pav, b23.x);
                ffma2(acc2[i][3], pav, b23.y);
            }
        }
        // no trailing barrier: next staging targets the other buffer
    }

    #pragma unroll
    for (int i = 0; i < 8; ++i) {
        int m = m0 + ((i < 4) ? (ty * 4 + i) : (64 + ty * 4 + i - 4));
        float bias = __ldg(&pb[m]);
        float* rp = &g_proj[m * PIXTOT + n0];
        float2 c0 = unpack2(acc2[i][0]);
        float2 c1 = unpack2(acc2[i][1]);
        float2 c2 = unpack2(acc2[i][2]);
        float2 c3 = unpack2(acc2[i][3]);
        float4 r0 = make_float4(c0.x + bias, c0.y + bias, c1.x + bias, c1.y + bias);
        float4 r1 = make_float4(c2.x + bias, c2.y + bias, c3.x + bias, c3.y + bias);
        *(float4*)&rp[tx * 4]      = r0;
        *(float4*)&rp[64 + tx * 4] = r1;
    }
}

// ---------------- K4: inverse wavelet (transposed depthwise 2x2) ------------
__global__ void iwt_kernel(const float* __restrict__ iwt, float* __restrict__ out) {
    int xo = threadIdx.x;          // 0..127
    int y  = blockIdx.x;           // 0..127
    int bc = blockIdx.y;           // 0..511
    int b  = bc >> 8, c = bc & 255;

    int base = (bc * H2 + y) * H2 + xo;
    float lh = g_lh[base], hl = g_hl[base], hh = g_hh[base];

    int wy = y >> 3, pyy = y & 7, wx = xo >> 3, pxx = xo & 7;
    int wdx = (b * 16 + wy) * 16 + wx;
    float ll = g_proj[c * PIXTOT + wdx * 64 + pyy * 8 + pxx];

    const float4 f0 = __ldg((const float4*)&iwt[(4 * c + 0) * 4]);
    const float4 f1 = __ldg((const float4*)&iwt[(4 * c + 1) * 4]);
    const float4 f2 = __ldg((const float4*)&iwt[(4 * c + 2) * 4]);
    const float4 f3 = __ldg((const float4*)&iwt[(4 * c + 3) * 4]);

    int ob = (bc * RESV + 2 * y) * RESV + 2 * xo;
    float2 r0 = make_float2(ll * f0.x + lh * f1.x + hl * f2.x + hh * f3.x,
                            ll * f0.y + lh * f1.y + hl * f2.y + hh * f3.y);
    float2 r1 = make_float2(ll * f0.z + lh * f1.z + hl * f2.z + hh * f3.z,
                            ll * f0.w + lh * f1.w + hl * f2.w + hh * f3.w);
    *(float2*)&out[ob]        = r0;
    *(float2*)&out[ob + RESV] = r1;
}

// ---------------- launch ----------------------------------------------------
extern "C" void kernel_launch(void* const* d_in, const int* in_sizes, int n_in,
                              void* d_out, int out_size) {
    const float* x    = (const float*)d_in[0];
    const float* wtf  = (const float*)d_in[1];
    const float* iwtf = (const float*)d_in[2];
    const float* dww  = (const float*)d_in[3];
    const float* dwb  = (const float*)d_in[4];
    const float* pw   = (const float*)d_in[5];
    const float* pb   = (const float*)d_in[6];
    const float* ab   = (const float*)d_in[7];
    const int*   bidx = (const int*)d_in[8];
    float* out = (float*)d_out;

    bias_kernel<<<128, 256>>>(ab, bidx);
    wt_kernel<<<dim3(128, 512), 128>>>(x, wtf);
    attn_mat_kernel<<<4096, 256>>>(dww, dwb);
    attn_av_kernel<<<1024, 128>>>();
    proj_gemm<<<dim3(256, 2), 256>>>(pw, pb);
    iwt_kernel<<<dim3(128, 512), 128>>>(iwtf, out);
}

// round 12
// speedup vs baseline: 1.0442x; 1.0442x over previous
#include <cuda_runtime.h>

#define DIMC 256
#define RESV 256
#define H2 128
#define HEADS 8
#define HD 32
#define NPIX 64
#define NWIN 512
#define PIXTOT (NWIN * NPIX)   // 32768
#define ATTN_SCALE 0.17677669529663687f
#define SROW 68                // padded smem row stride (floats)
#define AROW 68                // attn_av padded attn row stride
#define PSROW 132              // proj smem row stride (floats), 128-wide tiles

typedef unsigned long long ull;

// ---- packed fp32x2 helpers (FFMA2 — only reachable via PTX fma.rn.f32x2) ----
__device__ __forceinline__ void ffma2(ull& d, ull a, ull b) {
    asm("fma.rn.f32x2 %0, %1, %2, %0;" : "+l"(d) : "l"(a), "l"(b));
}
__device__ __forceinline__ ull pack2(float lo, float hi) {
    ull r; asm("mov.b64 %0, {%1, %2};" : "=l"(r) : "f"(lo), "f"(hi)); return r;
}
__device__ __forceinline__ float2 unpack2(ull v) {
    float2 r; asm("mov.b64 {%0, %1}, %2;" : "=f"(r.x), "=f"(r.y) : "l"(v)); return r;
}

// ---------------- scratch (static device allocations; no cudaMalloc) -------
__device__ float g_ll[2 * DIMC * H2 * H2];
__device__ float g_lh[2 * DIMC * H2 * H2];
__device__ float g_hl[2 * DIMC * H2 * H2];
__device__ float g_hh[2 * DIMC * H2 * H2];
__device__ float g_attn[NWIN * HEADS * NPIX * NPIX]; // softmax'd attn, [wh][n][m]
__device__ float g_att[DIMC * PIXTOT];    // relu(attention out), [c][pix]
__device__ float g_proj[DIMC * PIXTOT];   // proj out, [o][pix]
__device__ float g_bias[HEADS * NPIX * NPIX];

// ---------------- K0: expand attention bias table ---------------------------
__global__ void bias_kernel(const float* __restrict__ ab, const int* __restrict__ bidx) {
    int i = blockIdx.x * 256 + threadIdx.x;     // 32768 total
    int h = i >> 12;
    g_bias[i] = ab[h * 64 + bidx[i & 4095]];
}

// ---------------- K1: wavelet transform (depthwise 2x2 stride 2) -----------
__global__ void wt_kernel(const float* __restrict__ x, const float* __restrict__ wt) {
    int xo = threadIdx.x;          // 0..127
    int y  = blockIdx.x;           // 0..127
    int bc = blockIdx.y;           // 0..511 (b*256 + c)
    int c  = bc & 255;

    const float4 f0 = __ldg((const float4*)&wt[(4 * c + 0) * 4]);
    const float4 f1 = __ldg((const float4*)&wt[(4 * c + 1) * 4]);
    const float4 f2 = __ldg((const float4*)&wt[(4 * c + 2) * 4]);
    const float4 f3 = __ldg((const float4*)&wt[(4 * c + 3) * 4]);

    int ib = (bc * RESV + 2 * y) * RESV + 2 * xo;
    float2 p0 = *(const float2*)&x[ib];
    float2 p1 = *(const float2*)&x[ib + RESV];

    int ob = (bc * H2 + y) * H2 + xo;
    g_ll[ob] = p0.x * f0.x + p0.y * f0.y + p1.x * f0.z + p1.y * f0.w;
    g_lh[ob] = p0.x * f1.x + p0.y * f1.y + p1.x * f1.z + p1.y * f1.w;
    g_hl[ob] = p0.x * f2.x + p0.y * f2.y + p1.x * f2.z + p1.y * f2.w;
    g_hh[ob] = p0.x * f3.x + p0.y * f3.y + p1.x * f3.z + p1.y * f3.w;
}

// ---------------- K2a: attention matrices (all heads parallel) --------------
// One CTA per (window, head). Output stored [wh][n][m] — natural orientation,
// 4x STG.128 per thread.
__global__ __launch_bounds__(256) void attn_mat_kernel(
    const float* __restrict__ dww, const float* __restrict__ dwb) {
    __shared__ float lh_s[HD * SROW];
    __shared__ float k_s[HD * SROW];
    __shared__ float q_s[HD * SROW];
    __shared__ float w_s[HD * 25];

    const int t  = threadIdx.x;
    const int wh = blockIdx.x;           // 0..4095
    const int w  = wh >> 3;
    const int h  = wh & 7;
    const int b  = w >> 8;
    const int wy = (w >> 4) & 15;
    const int wx = w & 15;
    const int dl = t >> 3;               // 0..31
    const int py = t & 7;                // 0..7

    {
        int ch   = b * DIMC + h * HD + dl;
        int base = (ch * H2 + wy * 8 + py) * H2 + wx * 8;
        int o0   = dl * SROW + py * 8;
        *(float4*)&lh_s[o0]     = *(const float4*)&g_lh[base];
        *(float4*)&lh_s[o0 + 4] = *(const float4*)&g_lh[base + 4];
        *(float4*)&k_s[o0]      = *(const float4*)&g_hl[base];
        *(float4*)&k_s[o0 + 4]  = *(const float4*)&g_hl[base + 4];
    }
    for (int i = t; i < HD * 25; i += 256) w_s[i] = dww[h * HD * 25 + i];
    __syncthreads();

    // ---- q = depthwise 5x5 conv on lh ----
    {
        float accq[8];
        float bias0 = __ldg(&dwb[h * HD + dl]);
        #pragma unroll
        for (int px = 0; px < 8; ++px) accq[px] = bias0;
        #pragma unroll
        for (int u = 0; u < 5; ++u) {
            int yy = py + u - 2;
            if (yy >= 0 && yy < 8) {
                float4 r0 = *(const float4*)&lh_s[dl * SROW + yy * 8];
                float4 r1 = *(const float4*)&lh_s[dl * SROW + yy * 8 + 4];
                float r[8] = {r0.x, r0.y, r0.z, r0.w, r1.x, r1.y, r1.z, r1.w};
                #pragma unroll
                for (int v = 0; v < 5; ++v) {
                    float wv = w_s[dl * 25 + u * 5 + v];
                    #pragma unroll
                    for (int px = 0; px < 8; ++px) {
                        int xx = px + v - 2;
                        if (xx >= 0 && xx < 8)
                            accq[px] += r[xx] * wv;
                    }
                }
            }
        }
        #pragma unroll
        for (int px = 0; px < 8; ++px) q_s[dl * SROW + py * 8 + px] = accq[px];
    }
    __syncthreads();

    // ---- attn = softmax(q.k * scale + bias), packed f32x2 QK ----
    {
        int n  = t >> 2;
        int mq = t & 3;
        ull acc2[8];
        #pragma unroll
        for (int i = 0; i < 8; ++i) acc2[i] = 0ull;

        #pragma unroll 4
        for (int d2 = 0; d2 < HD; ++d2) {
            float qd = q_s[d2 * SROW + n];
            ull pq = pack2(qd, qd);
            const float* kp = &k_s[d2 * SROW + mq * 16];
            ulonglong2 k01 = *(const ulonglong2*)(kp);
            ulonglong2 k23 = *(const ulonglong2*)(kp + 4);
            ulonglong2 k45 = *(const ulonglong2*)(kp + 8);
            ulonglong2 k67 = *(const ulonglong2*)(kp + 12);
            ffma2(acc2[0], pq, k01.x);
            ffma2(acc2[1], pq, k01.y);
            ffma2(acc2[2], pq, k23.x);
            ffma2(acc2[3], pq, k23.y);
            ffma2(acc2[4], pq, k45.x);
            ffma2(acc2[5], pq, k45.y);
            ffma2(acc2[6], pq, k67.x);
            ffma2(acc2[7], pq, k67.y);
        }

        float acc[16];
        #pragma unroll
        for (int i = 0; i < 8; ++i) {
            float2 u = unpack2(acc2[i]);
            acc[2 * i]     = u.x;
            acc[2 * i + 1] = u.y;
        }

        const float* bptr = &g_bias[h * 4096 + n * 64 + mq * 16];
        float mx = -1e30f;
        #pragma unroll
        for (int mi = 0; mi < 16; ++mi) {
            acc[mi] = acc[mi] * ATTN_SCALE + __ldg(&bptr[mi]);
            mx = fmaxf(mx, acc[mi]);
        }
        mx = fmaxf(mx, __shfl_xor_sync(0xffffffffu, mx, 1));
        mx = fmaxf(mx, __shfl_xor_sync(0xffffffffu, mx, 2));
        float s = 0.f;
        #pragma unroll
        for (int mi = 0; mi < 16; ++mi) {
            float e = __expf(acc[mi] - mx);
            acc[mi] = e;
            s += e;
        }
        s += __shfl_xor_sync(0xffffffffu, s, 1);
        s += __shfl_xor_sync(0xffffffffu, s, 2);
        float inv = 1.f / s;

        // ---- [n][m] layout: contiguous in m -> 4x STG.128 ----
        float* op = &g_attn[wh * 4096 + n * 64 + mq * 16];
        #pragma unroll
        for (int g = 0; g < 4; ++g) {
            float4 r = make_float4(acc[4 * g + 0] * inv, acc[4 * g + 1] * inv,
                                   acc[4 * g + 2] * inv, acc[4 * g + 3] * inv);
            *(float4*)&op[g * 4] = r;
        }
    }
}

// ---------------- K2b: sequential AV chain, 2 CTAs per window (d-split) ----
// R9 structure (2 barriers/head, 25KB smem) with the attn tile staged in
// [n][m] layout (padded stride AROW): the FMA loop reads attn rows with
// LDS.128 instead of 8 scalar LDS.32 per step.
__global__ __launch_bounds__(128) void attn_av_kernel() {
    __shared__ float v_s[16 * NPIX];        // 4KB
    __shared__ float o_s[16 * NPIX];        // 4KB
    __shared__ float attn_s[NPIX * AROW];   // 17.4KB, [n][m] padded

    const int t    = threadIdx.x;           // 0..127
    const int wc   = blockIdx.x;            // 0..1023
    const int w    = wc >> 1;
    const int dbase = (wc & 1) * 16;        // d-half of this CTA
    const int b  = w >> 8;
    const int wy = (w >> 4) & 15;
    const int wx = w & 15;
    const int wp   = t >> 5;                // warp 0..3 -> local d rows 4wp..4wp+3
    const int lane = t & 31;                // n and n+32

    float4 pa[8];   // prefetched attn tile chunk ([n][m] linear)
    float4 pl[2];   // prefetched ll chunk

    {
        const float* ap = &g_attn[(w * 8 + 0) * 4096];
        #pragma unroll
        for (int i = 0; i < 8; ++i)
            pa[i] = *(const float4*)&ap[(t + 128 * i) * 4];
        #pragma unroll
        for (int i = 0; i < 2; ++i) {
            int c  = t + 128 * i;            // 0..255
            int d  = c >> 4;                 // 0..15 local
            int m0 = (c & 15) * 4;
            int ch = b * DIMC + 0 * HD + dbase + d;
            pl[i] = *(const float4*)&g_ll[(ch * H2 + wy * 8 + (m0 >> 3)) * H2
                                          + wx * 8 + (m0 & 7)];
        }
    }

    for (int h = 0; h < HEADS; ++h) {
        __syncthreads();

        // ---- stage attn into padded [n][m] smem ----
        #pragma unroll
        for (int i = 0; i < 8; ++i) {
            int c = t + 128 * i;             // linear chunk: n = c>>4, m0 = (c&15)*4
            *(float4*)&attn_s[(c >> 4) * AROW + (c & 15) * 4] = pa[i];
        }
        #pragma unroll
        for (int i = 0; i < 2; ++i) {
            int c = t + 128 * i;
            float4 v4 = pl[i];
            if (h > 0) {
                float4 o4 = *(const float4*)&o_s[c * 4];
                v4.x += o4.x; v4.y += o4.y; v4.z += o4.z; v4.w += o4.w;
                int d  = c >> 4;
                int m0 = (c & 15) * 4;
                float4 r = make_float4(fmaxf(o4.x, 0.f), fmaxf(o4.y, 0.f),
                                       fmaxf(o4.z, 0.f), fmaxf(o4.w, 0.f));
                *(float4*)&g_att[((h - 1) * HD + dbase + d) * PIXTOT + w * 64 + m0] = r;
            }
            *(float4*)&v_s[c * 4] = v4;
        }

        if (h < HEADS - 1) {
            const float* ap = &g_attn[(w * 8 + h + 1) * 4096];
            #pragma unroll
            for (int i = 0; i < 8; ++i)
                pa[i] = *(const float4*)&ap[(t + 128 * i) * 4];
            #pragma unroll
            for (int i = 0; i < 2; ++i) {
                int c  = t + 128 * i;
                int d  = c >> 4;
                int m0 = (c & 15) * 4;
                int ch = b * DIMC + (h + 1) * HD + dbase + d;
                pl[i] = *(const float4*)&g_ll[(ch * H2 + wy * 8 + (m0 >> 3)) * H2
                                              + wx * 8 + (m0 & 7)];
            }
        }
        __syncthreads();

        // ---- out[d][n] = sum_m v[d][m] * attn[n][m], FFMA2 pairs along m ----
        ull acc2[4][2];
        #pragma unroll
        for (int j = 0; j < 4; ++j) { acc2[j][0] = 0ull; acc2[j][1] = 0ull; }

        #pragma unroll
        for (int m = 0; m < 64; m += 4) {
            ulonglong2 va0 = *(const ulonglong2*)&v_s[(4 * wp + 0) * 64 + m];
            ulonglong2 va1 = *(const ulonglong2*)&v_s[(4 * wp + 1) * 64 + m];
            ulonglong2 va2 = *(const ulonglong2*)&v_s[(4 * wp + 2) * 64 + m];
            ulonglong2 va3 = *(const ulonglong2*)&v_s[(4 * wp + 3) * 64 + m];
            // attn rows for this thread's two n values: vector loads
            ulonglong2 al = *(const ulonglong2*)&attn_s[lane * AROW + m];
            ulonglong2 ah = *(const ulonglong2*)&attn_s[(lane + 32) * AROW + m];
            ffma2(acc2[0][0], va0.x, al.x); ffma2(acc2[0][0], va0.y, al.y);
            ffma2(acc2[1][0], va1.x, al.x); ffma2(acc2[1][0], va1.y, al.y);
            ffma2(acc2[2][0], va2.x, al.x); ffma2(acc2[2][0], va2.y, al.y);
            ffma2(acc2[3][0], va3.x, al.x); ffma2(acc2[3][0], va3.y, al.y);
            ffma2(acc2[0][1], va0.x, ah.x); ffma2(acc2[0][1], va0.y, ah.y);
            ffma2(acc2[1][1], va1.x, ah.x); ffma2(acc2[1][1], va1.y, ah.y);
            ffma2(acc2[2][1], va2.x, ah.x); ffma2(acc2[2][1], va2.y, ah.y);
            ffma2(acc2[3][1], va3.x, ah.x); ffma2(acc2[3][1], va3.y, ah.y);
        }
        #pragma unroll
        for (int j = 0; j < 4; ++j) {
            float2 u0 = unpack2(acc2[j][0]);
            float2 u1 = unpack2(acc2[j][1]);
            o_s[(4 * wp + j) * 64 + lane]      = u0.x + u0.y;
            o_s[(4 * wp + j) * 64 + lane + 32] = u1.x + u1.y;
        }
    }

    // ---- epilogue: relu-store head 7 output ----
    __syncthreads();
    #pragma unroll
    for (int i = 0; i < 2; ++i) {
        int c  = t + 128 * i;
        int d  = c >> 4;
        int m0 = (c & 15) * 4;
        float4 o4 = *(const float4*)&o_s[c * 4];
        float4 r = make_float4(fmaxf(o4.x, 0.f), fmaxf(o4.y, 0.f),
                               fmaxf(o4.z, 0.f), fmaxf(o4.w, 0.f));
        *(float4*)&g_att[(7 * HD + dbase + d) * PIXTOT + w * 64 + m0] = r;
    }
}

// ---------------- K3: proj GEMM  C[256,32768] = W[256,256] @ A + bias ------
// 128x128 tile, 8x8 micro-tile (packed f32x2), double-buffered smem:
// ONE __syncthreads per k-tile, warp skew allowed.
__global__ __launch_bounds__(256) void proj_gemm(
    const float* __restrict__ Wm, const float* __restrict__ pb) {
    __shared__ float As[2][16 * PSROW];
    __shared__ float Bs[2][16 * PSROW];

    const int t  = threadIdx.x;
    const int n0 = blockIdx.x * 128;
    const int m0 = blockIdx.y * 128;
    const int tx = t & 15, ty = t >> 4;

    const int am = t >> 1;
    const int ak = (t & 1) * 8;
    const int bk = t >> 4;
    const int bn = (t & 15) * 8;

    ull acc2[8][4];
    #pragma unroll
    for (int i = 0; i < 8; ++i)
        #pragma unroll
        for (int j = 0; j < 4; ++j) acc2[i][j] = 0ull;

    float4 pa0 = *(const float4*)&Wm[(m0 + am) * 256 + ak];
    float4 pa1 = *(const float4*)&Wm[(m0 + am) * 256 + ak + 4];
    float4 pb0 = *(const float4*)&g_att[bk * PIXTOT + n0 + bn];
    float4 pb1 = *(const float4*)&g_att[bk * PIXTOT + n0 + bn + 4];

    for (int kt = 0; kt < 16; ++kt) {
        float* as = As[kt & 1];
        float* bs = Bs[kt & 1];
        as[(ak + 0) * PSROW + am] = pa0.x;
        as[(ak + 1) * PSROW + am] = pa0.y;
        as[(ak + 2) * PSROW + am] = pa0.z;
        as[(ak + 3) * PSROW + am] = pa0.w;
        as[(ak + 4) * PSROW + am] = pa1.x;
        as[(ak + 5) * PSROW + am] = pa1.y;
        as[(ak + 6) * PSROW + am] = pa1.z;
        as[(ak + 7) * PSROW + am] = pa1.w;
        *(float4*)&bs[bk * PSROW + bn]     = pb0;
        *(float4*)&bs[bk * PSROW + bn + 4] = pb1;

        if (kt < 15) {
            int k0 = (kt + 1) * 16;
            pa0 = *(const float4*)&Wm[(m0 + am) * 256 + k0 + ak];
            pa1 = *(const float4*)&Wm[(m0 + am) * 256 + k0 + ak + 4];
            pb0 = *(const float4*)&g_att[(k0 + bk) * PIXTOT + n0 + bn];
            pb1 = *(const float4*)&g_att[(k0 + bk) * PIXTOT + n0 + bn + 4];
        }
        __syncthreads();   // staging of buf[kt&1] complete

        #pragma unroll
        for (int k = 0; k < 16; ++k) {
            float4 a0 = *(const float4*)&as[k * PSROW + ty * 4];
            float4 a1 = *(const float4*)&as[k * PSROW + 64 + ty * 4];
            ulonglong2 b01 = *(const ulonglong2*)&bs[k * PSROW + tx * 4];
            ulonglong2 b23 = *(const ulonglong2*)&bs[k * PSROW + 64 + tx * 4];
            float av[8] = {a0.x, a0.y, a0.z, a0.w, a1.x, a1.y, a1.z, a1.w};
            #pragma unroll
            for (int i = 0; i < 8; ++i) {
                ull pav = pack2(av[i], av[i]);
                ffma2(acc2[i][0], pav, b01.x);
                ffma2(acc2[i][1], pav, b01.y);
                ffma2(acc2[i][2], pav, b23.x);
                ffma2(acc2[i][3], pav, b23.y);
            }
        }
        // no trailing barrier: next staging targets the other buffer
    }

    #pragma unroll
    for (int i = 0; i < 8; ++i) {
        int m = m0 + ((i < 4) ? (ty * 4 + i) : (64 + ty * 4 + i - 4));
        float bias = __ldg(&pb[m]);
        float* rp = &g_proj[m * PIXTOT + n0];
        float2 c0 = unpack2(acc2[i][0]);
        float2 c1 = unpack2(acc2[i][1]);
        float2 c2 = unpack2(acc2[i][2]);
        float2 c3 = unpack2(acc2[i][3]);
        float4 r0 = make_float4(c0.x + bias, c0.y + bias, c1.x + bias, c1.y + bias);
        float4 r1 = make_float4(c2.x + bias, c2.y + bias, c3.x + bias, c3.y + bias);
        *(float4*)&rp[tx * 4]      = r0;
        *(float4*)&rp[64 + tx * 4] = r1;
    }
}

// ---------------- K4: inverse wavelet (transposed depthwise 2x2) ------------
__global__ void iwt_kernel(const float* __restrict__ iwt, float* __restrict__ out) {
    int xo = threadIdx.x;          // 0..127
    int y  = blockIdx.x;           // 0..127
    int bc = blockIdx.y;           // 0..511
    int b  = bc >> 8, c = bc & 255;

    int base = (bc * H2 + y) * H2 + xo;
    float lh = g_lh[base], hl = g_hl[base], hh = g_hh[base];

    int wy = y >> 3, pyy = y & 7, wx = xo >> 3, pxx = xo & 7;
    int wdx = (b * 16 + wy) * 16 + wx;
    float ll = g_proj[c * PIXTOT + wdx * 64 + pyy * 8 + pxx];

    const float4 f0 = __ldg((const float4*)&iwt[(4 * c + 0) * 4]);
    const float4 f1 = __ldg((const float4*)&iwt[(4 * c + 1) * 4]);
    const float4 f2 = __ldg((const float4*)&iwt[(4 * c + 2) * 4]);
    const float4 f3 = __ldg((const float4*)&iwt[(4 * c + 3) * 4]);

    int ob = (bc * RESV + 2 * y) * RESV + 2 * xo;
    float2 r0 = make_float2(ll * f0.x + lh * f1.x + hl * f2.x + hh * f3.x,
                            ll * f0.y + lh * f1.y + hl * f2.y + hh * f3.y);
    float2 r1 = make_float2(ll * f0.z + lh * f1.z + hl * f2.z + hh * f3.z,
                            ll * f0.w + lh * f1.w + hl * f2.w + hh * f3.w);
    *(float2*)&out[ob]        = r0;
    *(float2*)&out[ob + RESV] = r1;
}

// ---------------- launch ----------------------------------------------------
extern "C" void kernel_launch(void* const* d_in, const int* in_sizes, int n_in,
                              void* d_out, int out_size) {
    const float* x    = (const float*)d_in[0];
    const float* wtf  = (const float*)d_in[1];
    const float* iwtf = (const float*)d_in[2];
    const float* dww  = (const float*)d_in[3];
    const float* dwb  = (const float*)d_in[4];
    const float* pw   = (const float*)d_in[5];
    const float* pb   = (const float*)d_in[6];
    const float* ab   = (const float*)d_in[7];
    const int*   bidx = (const int*)d_in[8];
    float* out = (float*)d_out;

    bias_kernel<<<128, 256>>>(ab, bidx);
    wt_kernel<<<dim3(128, 512), 128>>>(x, wtf);
    attn_mat_kernel<<<4096, 256>>>(dww, dwb);
    attn_av_kernel<<<1024, 128>>>();
    proj_gemm<<<dim3(256, 2), 256>>>(pw, pb);
    iwt_kernel<<<dim3(128, 512), 128>>>(iwtf, out);
}

// round 13
// speedup vs baseline: 1.0822x; 1.0364x over previous
#include <cuda_runtime.h>
#include <cuda_fp16.h>

#define DIMC 256
#define RESV 256
#define H2 128
#define HEADS 8
#define HD 32
#define NPIX 64
#define NWIN 512
#define PIXTOT (NWIN * NPIX)   // 32768
#define ATTN_SCALE 0.17677669529663687f
#define SROW 68                // padded smem row stride (floats)
#define AROWH 72               // attn_av padded attn row stride (halfs, 144B rows)
#define PSROW 132              // proj smem row stride (floats), 128-wide tiles

typedef unsigned long long ull;

// ---- packed fp32x2 helpers (FFMA2 — only reachable via PTX fma.rn.f32x2) ----
__device__ __forceinline__ void ffma2(ull& d, ull a, ull b) {
    asm("fma.rn.f32x2 %0, %1, %2, %0;" : "+l"(d) : "l"(a), "l"(b));
}
__device__ __forceinline__ ull pack2(float lo, float hi) {
    ull r; asm("mov.b64 %0, {%1, %2};" : "=l"(r) : "f"(lo), "f"(hi)); return r;
}
__device__ __forceinline__ float2 unpack2(ull v) {
    float2 r; asm("mov.b64 {%0, %1}, %2;" : "=f"(r.x), "=f"(r.y) : "l"(v)); return r;
}
__device__ __forceinline__ ull h2_to_pack2(unsigned int h2) {
    float2 f = __half22float2(*(__half2*)&h2);
    return pack2(f.x, f.y);
}

// ---------------- scratch (static device allocations; no cudaMalloc) -------
__device__ float g_ll[2 * DIMC * H2 * H2];
__device__ float g_lh[2 * DIMC * H2 * H2];
__device__ float g_hl[2 * DIMC * H2 * H2];
__device__ float g_hh[2 * DIMC * H2 * H2];
__device__ __half g_attnh[NWIN * HEADS * NPIX * NPIX]; // softmax'd attn fp16, [wh][n][m]
__device__ float g_att[DIMC * PIXTOT];    // relu(attention out), [c][pix]
__device__ float g_proj[DIMC * PIXTOT];   // proj out, [o][pix]
__device__ float g_bias[HEADS * NPIX * NPIX];

// ---------------- K0: expand attention bias table ---------------------------
__global__ void bias_kernel(const float* __restrict__ ab, const int* __restrict__ bidx) {
    int i = blockIdx.x * 256 + threadIdx.x;     // 32768 total
    int h = i >> 12;
    g_bias[i] = ab[h * 64 + bidx[i & 4095]];
}

// ---------------- K1: wavelet transform (depthwise 2x2 stride 2) -----------
__global__ void wt_kernel(const float* __restrict__ x, const float* __restrict__ wt) {
    int xo = threadIdx.x;          // 0..127
    int y  = blockIdx.x;           // 0..127
    int bc = blockIdx.y;           // 0..511 (b*256 + c)
    int c  = bc & 255;

    const float4 f0 = __ldg((const float4*)&wt[(4 * c + 0) * 4]);
    const float4 f1 = __ldg((const float4*)&wt[(4 * c + 1) * 4]);
    const float4 f2 = __ldg((const float4*)&wt[(4 * c + 2) * 4]);
    const float4 f3 = __ldg((const float4*)&wt[(4 * c + 3) * 4]);

    int ib = (bc * RESV + 2 * y) * RESV + 2 * xo;
    float2 p0 = *(const float2*)&x[ib];
    float2 p1 = *(const float2*)&x[ib + RESV];

    int ob = (bc * H2 + y) * H2 + xo;
    g_ll[ob] = p0.x * f0.x + p0.y * f0.y + p1.x * f0.z + p1.y * f0.w;
    g_lh[ob] = p0.x * f1.x + p0.y * f1.y + p1.x * f1.z + p1.y * f1.w;
    g_hl[ob] = p0.x * f2.x + p0.y * f2.y + p1.x * f2.z + p1.y * f2.w;
    g_hh[ob] = p0.x * f3.x + p0.y * f3.y + p1.x * f3.z + p1.y * f3.w;
}

// ---------------- K2a: attention matrices (all heads parallel) --------------
// One CTA per (window, head). Output stored [wh][n][m] as fp16 — 2x STG.128.
__global__ __launch_bounds__(256) void attn_mat_kernel(
    const float* __restrict__ dww, const float* __restrict__ dwb) {
    __shared__ float lh_s[HD * SROW];
    __shared__ float k_s[HD * SROW];
    __shared__ float q_s[HD * SROW];
    __shared__ float w_s[HD * 25];

    const int t  = threadIdx.x;
    const int wh = blockIdx.x;           // 0..4095
    const int w  = wh >> 3;
    const int h  = wh & 7;
    const int b  = w >> 8;
    const int wy = (w >> 4) & 15;
    const int wx = w & 15;
    const int dl = t >> 3;               // 0..31
    const int py = t & 7;                // 0..7

    {
        int ch   = b * DIMC + h * HD + dl;
        int base = (ch * H2 + wy * 8 + py) * H2 + wx * 8;
        int o0   = dl * SROW + py * 8;
        *(float4*)&lh_s[o0]     = *(const float4*)&g_lh[base];
        *(float4*)&lh_s[o0 + 4] = *(const float4*)&g_lh[base + 4];
        *(float4*)&k_s[o0]      = *(const float4*)&g_hl[base];
        *(float4*)&k_s[o0 + 4]  = *(const float4*)&g_hl[base + 4];
    }
    for (int i = t; i < HD * 25; i += 256) w_s[i] = dww[h * HD * 25 + i];
    __syncthreads();

    // ---- q = depthwise 5x5 conv on lh ----
    {
        float accq[8];
        float bias0 = __ldg(&dwb[h * HD + dl]);
        #pragma unroll
        for (int px = 0; px < 8; ++px) accq[px] = bias0;
        #pragma unroll
        for (int u = 0; u < 5; ++u) {
            int yy = py + u - 2;
            if (yy >= 0 && yy < 8) {
                float4 r0 = *(const float4*)&lh_s[dl * SROW + yy * 8];
                float4 r1 = *(const float4*)&lh_s[dl * SROW + yy * 8 + 4];
                float r[8] = {r0.x, r0.y, r0.z, r0.w, r1.x, r1.y, r1.z, r1.w};
                #pragma unroll
                for (int v = 0; v < 5; ++v) {
                    float wv = w_s[dl * 25 + u * 5 + v];
                    #pragma unroll
                    for (int px = 0; px < 8; ++px) {
                        int xx = px + v - 2;
                        if (xx >= 0 && xx < 8)
                            accq[px] += r[xx] * wv;
                    }
                }
            }
        }
        #pragma unroll
        for (int px = 0; px < 8; ++px) q_s[dl * SROW + py * 8 + px] = accq[px];
    }
    __syncthreads();

    // ---- attn = softmax(q.k * scale + bias), packed f32x2 QK ----
    {
        int n  = t >> 2;
        int mq = t & 3;
        ull acc2[8];
        #pragma unroll
        for (int i = 0; i < 8; ++i) acc2[i] = 0ull;

        #pragma unroll 4
        for (int d2 = 0; d2 < HD; ++d2) {
            float qd = q_s[d2 * SROW + n];
            ull pq = pack2(qd, qd);
            const float* kp = &k_s[d2 * SROW + mq * 16];
            ulonglong2 k01 = *(const ulonglong2*)(kp);
            ulonglong2 k23 = *(const ulonglong2*)(kp + 4);
            ulonglong2 k45 = *(const ulonglong2*)(kp + 8);
            ulonglong2 k67 = *(const ulonglong2*)(kp + 12);
            ffma2(acc2[0], pq, k01.x);
            ffma2(acc2[1], pq, k01.y);
            ffma2(acc2[2], pq, k23.x);
            ffma2(acc2[3], pq, k23.y);
            ffma2(acc2[4], pq, k45.x);
            ffma2(acc2[5], pq, k45.y);
            ffma2(acc2[6], pq, k67.x);
            ffma2(acc2[7], pq, k67.y);
        }

        float acc[16];
        #pragma unroll
        for (int i = 0; i < 8; ++i) {
            float2 u = unpack2(acc2[i]);
            acc[2 * i]     = u.x;
            acc[2 * i + 1] = u.y;
        }

        const float* bptr = &g_bias[h * 4096 + n * 64 + mq * 16];
        float mx = -1e30f;
        #pragma unroll
        for (int mi = 0; mi < 16; ++mi) {
            acc[mi] = acc[mi] * ATTN_SCALE + __ldg(&bptr[mi]);
            mx = fmaxf(mx, acc[mi]);
        }
        mx = fmaxf(mx, __shfl_xor_sync(0xffffffffu, mx, 1));
        mx = fmaxf(mx, __shfl_xor_sync(0xffffffffu, mx, 2));
        float s = 0.f;
        #pragma unroll
        for (int mi = 0; mi < 16; ++mi) {
            float e = __expf(acc[mi] - mx);
            acc[mi] = e;
            s += e;
        }
        s += __shfl_xor_sync(0xffffffffu, s, 1);
        s += __shfl_xor_sync(0xffffffffu, s, 2);
        float inv = 1.f / s;

        // ---- fp16 [n][m] layout: 16 halfs contiguous -> 2x STG.128 ----
        __half2 hb[8];
        #pragma unroll
        for (int g2 = 0; g2 < 8; ++g2)
            hb[g2] = __floats2half2_rn(acc[2 * g2] * inv, acc[2 * g2 + 1] * inv);
        __half* op = &g_attnh[wh * 4096 + n * 64 + mq * 16];
        *(uint4*)op       = *(uint4*)&hb[0];
        *(uint4*)(op + 8) = *(uint4*)&hb[4];
    }
}

// ---------------- K2b: sequential AV chain, 2 CTAs per window (d-split) ----
// attn tile staged as fp16 [n][m] (AROWH=72 halfs -> 144B rows, conflict-free
// LDS.128 of 8 halfs). FMA loop runs 8-m steps, converting half2->f32x2 pairs
// feeding FFMA2. Prefetch regs halved vs fp32 tile.
__global__ __launch_bounds__(128) void attn_av_kernel() {
    __shared__ float v_s[16 * NPIX];          // 4KB
    __shared__ float o_s[16 * NPIX];          // 4KB
    __shared__ __half attn_h[NPIX * AROWH];   // 9KB, fp16 [n][m] padded

    const int t    = threadIdx.x;           // 0..127
    const int wc   = blockIdx.x;            // 0..1023
    const int w    = wc >> 1;
    const int dbase = (wc & 1) * 16;        // d-half of this CTA
    const int b  = w >> 8;
    const int wy = (w >> 4) & 15;
    const int wx = w & 15;
    const int wp   = t >> 5;                // warp 0..3 -> local d rows 4wp..4wp+3
    const int lane = t & 31;                // n and n+32

    uint4 pa[4];    // prefetched fp16 attn tile (8KB / 128 threads = 4 uint4)
    float4 pl[2];   // prefetched ll chunk

    {
        const uint4* ap = (const uint4*)&g_attnh[(w * 8 + 0) * 4096];
        #pragma unroll
        for (int i = 0; i < 4; ++i)
            pa[i] = ap[t + 128 * i];
        #pragma unroll
        for (int i = 0; i < 2; ++i) {
            int c  = t + 128 * i;            // 0..255
            int d  = c >> 4;                 // 0..15 local
            int m0 = (c & 15) * 4;
            int ch = b * DIMC + 0 * HD + dbase + d;
            pl[i] = *(const float4*)&g_ll[(ch * H2 + wy * 8 + (m0 >> 3)) * H2
                                          + wx * 8 + (m0 & 7)];
        }
    }

    for (int h = 0; h < HEADS; ++h) {
        __syncthreads();

        // ---- stage fp16 attn into padded [n][m] smem ----
        #pragma unroll
        for (int i = 0; i < 4; ++i) {
            int c = t + 128 * i;             // 0..511: n = c>>3, m0 = (c&7)*8
            *(uint4*)&attn_h[(c >> 3) * AROWH + (c & 7) * 8] = pa[i];
        }
        #pragma unroll
        for (int i = 0; i < 2; ++i) {
            int c = t + 128 * i;
            float4 v4 = pl[i];
            if (h > 0) {
                float4 o4 = *(const float4*)&o_s[c * 4];
                v4.x += o4.x; v4.y += o4.y; v4.z += o4.z; v4.w += o4.w;
                int d  = c >> 4;
                int m0 = (c & 15) * 4;
                float4 r = make_float4(fmaxf(o4.x, 0.f), fmaxf(o4.y, 0.f),
                                       fmaxf(o4.z, 0.f), fmaxf(o4.w, 0.f));
                *(float4*)&g_att[((h - 1) * HD + dbase + d) * PIXTOT + w * 64 + m0] = r;
            }
            *(float4*)&v_s[c * 4] = v4;
        }

        if (h < HEADS - 1) {
            const uint4* ap = (const uint4*)&g_attnh[(w * 8 + h + 1) * 4096];
            #pragma unroll
            for (int i = 0; i < 4; ++i)
                pa[i] = ap[t + 128 * i];
            #pragma unroll
            for (int i = 0; i < 2; ++i) {
                int c  = t + 128 * i;
                int d  = c >> 4;
                int m0 = (c & 15) * 4;
                int ch = b * DIMC + (h + 1) * HD + dbase + d;
                pl[i] = *(const float4*)&g_ll[(ch * H2 + wy * 8 + (m0 >> 3)) * H2
                                              + wx * 8 + (m0 & 7)];
            }
        }
        __syncthreads();

        // ---- out[d][n] = sum_m v[d][m] * attn[n][m], 8-m steps ----
        ull acc2[4][2];
        #pragma unroll
        for (int j = 0; j < 4; ++j) { acc2[j][0] = 0ull; acc2[j][1] = 0ull; }

        #pragma unroll
        for (int m = 0; m < 64; m += 8) {
            // attn rows for this thread's two n values: 8 halfs each, LDS.128
            uint4 alh = *(const uint4*)&attn_h[lane * AROWH + m];
            uint4 ahh = *(const uint4*)&attn_h[(lane + 32) * AROWH + m];
            ull AL0 = h2_to_pack2(alh.x), AL1 = h2_to_pack2(alh.y);
            ull AL2 = h2_to_pack2(alh.z), AL3 = h2_to_pack2(alh.w);
            ull AH0 = h2_to_pack2(ahh.x), AH1 = h2_to_pack2(ahh.y);
            ull AH2 = h2_to_pack2(ahh.z), AH3 = h2_to_pack2(ahh.w);

            #pragma unroll
            for (int j = 0; j < 4; ++j) {
                ulonglong2 va = *(const ulonglong2*)&v_s[(4 * wp + j) * 64 + m];
                ulonglong2 vb = *(const ulonglong2*)&v_s[(4 * wp + j) * 64 + m + 4];
                ffma2(acc2[j][0], va.x, AL0); ffma2(acc2[j][0], va.y, AL1);
                ffma2(acc2[j][0], vb.x, AL2); ffma2(acc2[j][0], vb.y, AL3);
                ffma2(acc2[j][1], va.x, AH0); ffma2(acc2[j][1], va.y, AH1);
                ffma2(acc2[j][1], vb.x, AH2); ffma2(acc2[j][1], vb.y, AH3);
            }
        }
        #pragma unroll
        for (int j = 0; j < 4; ++j) {
            float2 u0 = unpack2(acc2[j][0]);
            float2 u1 = unpack2(acc2[j][1]);
            o_s[(4 * wp + j) * 64 + lane]      = u0.x + u0.y;
            o_s[(4 * wp + j) * 64 + lane + 32] = u1.x + u1.y;
        }
    }

    // ---- epilogue: relu-store head 7 output ----
    __syncthreads();
    #pragma unroll
    for (int i = 0; i < 2; ++i) {
        int c  = t + 128 * i;
        int d  = c >> 4;
        int m0 = (c & 15) * 4;
        float4 o4 = *(const float4*)&o_s[c * 4];
        float4 r = make_float4(fmaxf(o4.x, 0.f), fmaxf(o4.y, 0.f),
                               fmaxf(o4.z, 0.f), fmaxf(o4.w, 0.f));
        *(float4*)&g_att[(7 * HD + dbase + d) * PIXTOT + w * 64 + m0] = r;
    }
}

// ---------------- K3: proj GEMM  C[256,32768] = W[256,256] @ A + bias ------
// 128x128 tile, 8x8 micro-tile (packed f32x2), double-buffered smem:
// ONE __syncthreads per k-tile, warp skew allowed.
__global__ __launch_bounds__(256) void proj_gemm(
    const float* __restrict__ Wm, const float* __restrict__ pb) {
    __shared__ float As[2][16 * PSROW];
    __shared__ float Bs[2][16 * PSROW];

    const int t  = threadIdx.x;
    const int n0 = blockIdx.x * 128;
    const int m0 = blockIdx.y * 128;
    const int tx = t & 15, ty = t >> 4;

    const int am = t >> 1;
    const int ak = (t & 1) * 8;
    const int bk = t >> 4;
    const int bn = (t & 15) * 8;

    ull acc2[8][4];
    #pragma unroll
    for (int i = 0; i < 8; ++i)
        #pragma unroll
        for (int j = 0; j < 4; ++j) acc2[i][j] = 0ull;

    float4 pa0 = *(const float4*)&Wm[(m0 + am) * 256 + ak];
    float4 pa1 = *(const float4*)&Wm[(m0 + am) * 256 + ak + 4];
    float4 pb0 = *(const float4*)&g_att[bk * PIXTOT + n0 + bn];
    float4 pb1 = *(const float4*)&g_att[bk * PIXTOT + n0 + bn + 4];

    for (int kt = 0; kt < 16; ++kt) {
        float* as = As[kt & 1];
        float* bs = Bs[kt & 1];
        as[(ak + 0) * PSROW + am] = pa0.x;
        as[(ak + 1) * PSROW + am] = pa0.y;
        as[(ak + 2) * PSROW + am] = pa0.z;
        as[(ak + 3) * PSROW + am] = pa0.w;
        as[(ak + 4) * PSROW + am] = pa1.x;
        as[(ak + 5) * PSROW + am] = pa1.y;
        as[(ak + 6) * PSROW + am] = pa1.z;
        as[(ak + 7) * PSROW + am] = pa1.w;
        *(float4*)&bs[bk * PSROW + bn]     = pb0;
        *(float4*)&bs[bk * PSROW + bn + 4] = pb1;

        if (kt < 15) {
            int k0 = (kt + 1) * 16;
            pa0 = *(const float4*)&Wm[(m0 + am) * 256 + k0 + ak];
            pa1 = *(const float4*)&Wm[(m0 + am) * 256 + k0 + ak + 4];
            pb0 = *(const float4*)&g_att[(k0 + bk) * PIXTOT + n0 + bn];
            pb1 = *(const float4*)&g_att[(k0 + bk) * PIXTOT + n0 + bn + 4];
        }
        __syncthreads();   // staging of buf[kt&1] complete

        #pragma unroll
        for (int k = 0; k < 16; ++k) {
            float4 a0 = *(const float4*)&as[k * PSROW + ty * 4];
            float4 a1 = *(const float4*)&as[k * PSROW + 64 + ty * 4];
            ulonglong2 b01 = *(const ulonglong2*)&bs[k * PSROW + tx * 4];
            ulonglong2 b23 = *(const ulonglong2*)&bs[k * PSROW + 64 + tx * 4];
            float av[8] = {a0.x, a0.y, a0.z, a0.w, a1.x, a1.y, a1.z, a1.w};
            #pragma unroll
            for (int i = 0; i < 8; ++i) {
                ull pav = pack2(av[i], av[i]);
                ffma2(acc2[i][0], pav, b01.x);
                ffma2(acc2[i][1], pav, b01.y);
                ffma2(acc2[i][2], pav, b23.x);
                ffma2(acc2[i][3], pav, b23.y);
            }
        }
        // no trailing barrier: next staging targets the other buffer
    }

    #pragma unroll
    for (int i = 0; i < 8; ++i) {
        int m = m0 + ((i < 4) ? (ty * 4 + i) : (64 + ty * 4 + i - 4));
        float bias = __ldg(&pb[m]);
        float* rp = &g_proj[m * PIXTOT + n0];
        float2 c0 = unpack2(acc2[i][0]);
        float2 c1 = unpack2(acc2[i][1]);
        float2 c2 = unpack2(acc2[i][2]);
        float2 c3 = unpack2(acc2[i][3]);
        float4 r0 = make_float4(c0.x + bias, c0.y + bias, c1.x + bias, c1.y + bias);
        float4 r1 = make_float4(c2.x + bias, c2.y + bias, c3.x + bias, c3.y + bias);
        *(float4*)&rp[tx * 4]      = r0;
        *(float4*)&rp[64 + tx * 4] = r1;
    }
}

// ---------------- K4: inverse wavelet (transposed depthwise 2x2) ------------
__global__ void iwt_kernel(const float* __restrict__ iwt, float* __restrict__ out) {
    int xo = threadIdx.x;          // 0..127
    int y  = blockIdx.x;           // 0..127
    int bc = blockIdx.y;           // 0..511
    int b  = bc >> 8, c = bc & 255;

    int base = (bc * H2 + y) * H2 + xo;
    float lh = g_lh[base], hl = g_hl[base], hh = g_hh[base];

    int wy = y >> 3, pyy = y & 7, wx = xo >> 3, pxx = xo & 7;
    int wdx = (b * 16 + wy) * 16 + wx;
    float ll = g_proj[c * PIXTOT + wdx * 64 + pyy * 8 + pxx];

    const float4 f0 = __ldg((const float4*)&iwt[(4 * c + 0) * 4]);
    const float4 f1 = __ldg((const float4*)&iwt[(4 * c + 1) * 4]);
    const float4 f2 = __ldg((const float4*)&iwt[(4 * c + 2) * 4]);
    const float4 f3 = __ldg((const float4*)&iwt[(4 * c + 3) * 4]);

    int ob = (bc * RESV + 2 * y) * RESV + 2 * xo;
    float2 r0 = make_float2(ll * f0.x + lh * f1.x + hl * f2.x + hh * f3.x,
                            ll * f0.y + lh * f1.y + hl * f2.y + hh * f3.y);
    float2 r1 = make_float2(ll * f0.z + lh * f1.z + hl * f2.z + hh * f3.z,
                            ll * f0.w + lh * f1.w + hl * f2.w + hh * f3.w);
    *(float2*)&out[ob]        = r0;
    *(float2*)&out[ob + RESV] = r1;
}

// ---------------- launch ----------------------------------------------------
extern "C" void kernel_launch(void* const* d_in, const int* in_sizes, int n_in,
                              void* d_out, int out_size) {
    const float* x    = (const float*)d_in[0];
    const float* wtf  = (const float*)d_in[1];
    const float* iwtf = (const float*)d_in[2];
    const float* dww  = (const float*)d_in[3];
    const float* dwb  = (const float*)d_in[4];
    const float* pw   = (const float*)d_in[5];
    const float* pb   = (const float*)d_in[6];
    const float* ab   = (const float*)d_in[7];
    const int*   bidx = (const int*)d_in[8];
    float* out = (float*)d_out;

    bias_kernel<<<128, 256>>>(ab, bidx);
    wt_kernel<<<dim3(128, 512), 128>>>(x, wtf);
    attn_mat_kernel<<<4096, 256>>>(dww, dwb);
    attn_av_kernel<<<1024, 128>>>();
    proj_gemm<<<dim3(256, 2), 256>>>(pw, pb);
    iwt_kernel<<<dim3(128, 512), 128>>>(iwtf, out);
}

// round 14
// speedup vs baseline: 1.1110x; 1.0267x over previous
#include <cuda_runtime.h>
#include <cuda_fp16.h>

#define DIMC 256
#define RESV 256
#define H2 128
#define HEADS 8
#define HD 32
#define NPIX 64
#define NWIN 512
#define PIXTOT (NWIN * NPIX)   // 32768
#define ATTN_SCALE 0.17677669529663687f
#define SROW 68                // padded smem row stride (floats)
#define AROWH 72               // attn_av padded attn row stride (halfs, 144B rows)
#define PSROW 132              // proj smem row stride (floats), 128-wide tiles

typedef unsigned long long ull;

// ---- packed fp32x2 helpers (FFMA2 — only reachable via PTX fma.rn.f32x2) ----
__device__ __forceinline__ void ffma2(ull& d, ull a, ull b) {
    asm("fma.rn.f32x2 %0, %1, %2, %0;" : "+l"(d) : "l"(a), "l"(b));
}
__device__ __forceinline__ ull pack2(float lo, float hi) {
    ull r; asm("mov.b64 %0, {%1, %2};" : "=l"(r) : "f"(lo), "f"(hi)); return r;
}
__device__ __forceinline__ float2 unpack2(ull v) {
    float2 r; asm("mov.b64 {%0, %1}, %2;" : "=f"(r.x), "=f"(r.y) : "l"(v)); return r;
}
__device__ __forceinline__ ull h2_to_pack2(unsigned int h2) {
    float2 f = __half22float2(*(__half2*)&h2);
    return pack2(f.x, f.y);
}

// ---------------- scratch (static device allocations; no cudaMalloc) -------
__device__ float g_ll[2 * DIMC * H2 * H2];
__device__ float g_lh[2 * DIMC * H2 * H2];
__device__ float g_hl[2 * DIMC * H2 * H2];
__device__ float g_hh[2 * DIMC * H2 * H2];
__device__ __half g_attnh[NWIN * HEADS * NPIX * NPIX]; // softmax'd attn fp16, [wh][n][m]
__device__ __half g_atth[DIMC * PIXTOT];  // relu(attention out) fp16, [c][pix]
__device__ float g_proj[DIMC * PIXTOT];   // proj out fp32, [o][pix]
__device__ float g_bias[HEADS * NPIX * NPIX];

// ---------------- K0: expand attention bias table ---------------------------
__global__ void bias_kernel(const float* __restrict__ ab, const int* __restrict__ bidx) {
    int i = blockIdx.x * 256 + threadIdx.x;     // 32768 total
    int h = i >> 12;
    g_bias[i] = ab[h * 64 + bidx[i & 4095]];
}

// ---------------- K1: wavelet transform (depthwise 2x2 stride 2) -----------
// 2 output pixels per thread: 2x LDG.128, 16 FFMA2, 4x STG.64
__global__ void wt_kernel(const float* __restrict__ x, const float* __restrict__ wt) {
    int t  = threadIdx.x;          // 0..127
    int tx = t & 63;               // x-pair index: outputs x = 2tx, 2tx+1
    int y  = 2 * blockIdx.x + (t >> 6);   // 0..127
    int bc = blockIdx.y;           // 0..511
    int c  = bc & 255;

    const float4 f0 = __ldg((const float4*)&wt[(4 * c + 0) * 4]);
    const float4 f1 = __ldg((const float4*)&wt[(4 * c + 1) * 4]);
    const float4 f2 = __ldg((const float4*)&wt[(4 * c + 2) * 4]);
    const float4 f3 = __ldg((const float4*)&wt[(4 * c + 3) * 4]);

    int ib = (bc * RESV + 2 * y) * RESV + 4 * tx;
    float4 p0 = *(const float4*)&x[ib];
    float4 p1 = *(const float4*)&x[ib + RESV];

    // packed across the two output pixels
    ull A0 = pack2(p0.x, p0.z), A1 = pack2(p0.y, p0.w);
    ull A2 = pack2(p1.x, p1.z), A3 = pack2(p1.y, p1.w);

    ull r0 = 0, r1 = 0, r2 = 0, r3 = 0;
    ffma2(r0, A0, pack2(f0.x, f0.x)); ffma2(r0, A1, pack2(f0.y, f0.y));
    ffma2(r0, A2, pack2(f0.z, f0.z)); ffma2(r0, A3, pack2(f0.w, f0.w));
    ffma2(r1, A0, pack2(f1.x, f1.x)); ffma2(r1, A1, pack2(f1.y, f1.y));
    ffma2(r1, A2, pack2(f1.z, f1.z)); ffma2(r1, A3, pack2(f1.w, f1.w));
    ffma2(r2, A0, pack2(f2.x, f2.x)); ffma2(r2, A1, pack2(f2.y, f2.y));
    ffma2(r2, A2, pack2(f2.z, f2.z)); ffma2(r2, A3, pack2(f2.w, f2.w));
    ffma2(r3, A0, pack2(f3.x, f3.x)); ffma2(r3, A1, pack2(f3.y, f3.y));
    ffma2(r3, A2, pack2(f3.z, f3.z)); ffma2(r3, A3, pack2(f3.w, f3.w));

    int ob = (bc * H2 + y) * H2 + 2 * tx;
    *(float2*)&g_ll[ob] = unpack2(r0);
    *(float2*)&g_lh[ob] = unpack2(r1);
    *(float2*)&g_hl[ob] = unpack2(r2);
    *(float2*)&g_hh[ob] = unpack2(r3);
}

// ---------------- K2a: attention matrices (all heads parallel) --------------
// One CTA per (window, head). Output stored [wh][n][m] as fp16 — 2x STG.128.
__global__ __launch_bounds__(256) void attn_mat_kernel(
    const float* __restrict__ dww, const float* __restrict__ dwb) {
    __shared__ float lh_s[HD * SROW];
    __shared__ float k_s[HD * SROW];
    __shared__ float q_s[HD * SROW];
    __shared__ float w_s[HD * 25];

    const int t  = threadIdx.x;
    const int wh = blockIdx.x;           // 0..4095
    const int w  = wh >> 3;
    const int h  = wh & 7;
    const int b  = w >> 8;
    const int wy = (w >> 4) & 15;
    const int wx = w & 15;
    const int dl = t >> 3;               // 0..31
    const int py = t & 7;                // 0..7

    {
        int ch   = b * DIMC + h * HD + dl;
        int base = (ch * H2 + wy * 8 + py) * H2 + wx * 8;
        int o0   = dl * SROW + py * 8;
        *(float4*)&lh_s[o0]     = *(const float4*)&g_lh[base];
        *(float4*)&lh_s[o0 + 4] = *(const float4*)&g_lh[base + 4];
        *(float4*)&k_s[o0]      = *(const float4*)&g_hl[base];
        *(float4*)&k_s[o0 + 4]  = *(const float4*)&g_hl[base + 4];
    }
    for (int i = t; i < HD * 25; i += 256) w_s[i] = dww[h * HD * 25 + i];
    __syncthreads();

    // ---- q = depthwise 5x5 conv on lh ----
    {
        float accq[8];
        float bias0 = __ldg(&dwb[h * HD + dl]);
        #pragma unroll
        for (int px = 0; px < 8; ++px) accq[px] = bias0;
        #pragma unroll
        for (int u = 0; u < 5; ++u) {
            int yy = py + u - 2;
            if (yy >= 0 && yy < 8) {
                float4 r0 = *(const float4*)&lh_s[dl * SROW + yy * 8];
                float4 r1 = *(const float4*)&lh_s[dl * SROW + yy * 8 + 4];
                float r[8] = {r0.x, r0.y, r0.z, r0.w, r1.x, r1.y, r1.z, r1.w};
                #pragma unroll
                for (int v = 0; v < 5; ++v) {
                    float wv = w_s[dl * 25 + u * 5 + v];
                    #pragma unroll
                    for (int px = 0; px < 8; ++px) {
                        int xx = px + v - 2;
                        if (xx >= 0 && xx < 8)
                            accq[px] += r[xx] * wv;
                    }
                }
            }
        }
        #pragma unroll
        for (int px = 0; px < 8; ++px) q_s[dl * SROW + py * 8 + px] = accq[px];
    }
    __syncthreads();

    // ---- attn = softmax(q.k * scale + bias), packed f32x2 QK ----
    {
        int n  = t >> 2;
        int mq = t & 3;
        ull acc2[8];
        #pragma unroll
        for (int i = 0; i < 8; ++i) acc2[i] = 0ull;

        #pragma unroll 4
        for (int d2 = 0; d2 < HD; ++d2) {
            float qd = q_s[d2 * SROW + n];
            ull pq = pack2(qd, qd);
            const float* kp = &k_s[d2 * SROW + mq * 16];
            ulonglong2 k01 = *(const ulonglong2*)(kp);
            ulonglong2 k23 = *(const ulonglong2*)(kp + 4);
            ulonglong2 k45 = *(const ulonglong2*)(kp + 8);
            ulonglong2 k67 = *(const ulonglong2*)(kp + 12);
            ffma2(acc2[0], pq, k01.x);
            ffma2(acc2[1], pq, k01.y);
            ffma2(acc2[2], pq, k23.x);
            ffma2(acc2[3], pq, k23.y);
            ffma2(acc2[4], pq, k45.x);
            ffma2(acc2[5], pq, k45.y);
            ffma2(acc2[6], pq, k67.x);
            ffma2(acc2[7], pq, k67.y);
        }

        float acc[16];
        #pragma unroll
        for (int i = 0; i < 8; ++i) {
            float2 u = unpack2(acc2[i]);
            acc[2 * i]     = u.x;
            acc[2 * i + 1] = u.y;
        }

        const float* bptr = &g_bias[h * 4096 + n * 64 + mq * 16];
        float mx = -1e30f;
        #pragma unroll
        for (int mi = 0; mi < 16; ++mi) {
            acc[mi] = acc[mi] * ATTN_SCALE + __ldg(&bptr[mi]);
            mx = fmaxf(mx, acc[mi]);
        }
        mx = fmaxf(mx, __shfl_xor_sync(0xffffffffu, mx, 1));
        mx = fmaxf(mx, __shfl_xor_sync(0xffffffffu, mx, 2));
        float s = 0.f;
        #pragma unroll
        for (int mi = 0; mi < 16; ++mi) {
            float e = __expf(acc[mi] - mx);
            acc[mi] = e;
            s += e;
        }
        s += __shfl_xor_sync(0xffffffffu, s, 1);
        s += __shfl_xor_sync(0xffffffffu, s, 2);
        float inv = 1.f / s;

        // ---- fp16 [n][m] layout: 16 halfs contiguous -> 2x STG.128 ----
        __half2 hb[8];
        #pragma unroll
        for (int g2 = 0; g2 < 8; ++g2)
            hb[g2] = __floats2half2_rn(acc[2 * g2] * inv, acc[2 * g2 + 1] * inv);
        __half* op = &g_attnh[wh * 4096 + n * 64 + mq * 16];
        *(uint4*)op       = *(uint4*)&hb[0];
        *(uint4*)(op + 8) = *(uint4*)&hb[4];
    }
}

// ---------------- K2b: sequential AV chain, 2 CTAs per window (d-split) ----
// fp16 attn tile ([n][m], AROWH=72), fp16 relu output.
__global__ __launch_bounds__(128) void attn_av_kernel() {
    __shared__ float v_s[16 * NPIX];          // 4KB
    __shared__ float o_s[16 * NPIX];          // 4KB
    __shared__ __half attn_h[NPIX * AROWH];   // 9KB, fp16 [n][m] padded

    const int t    = threadIdx.x;           // 0..127
    const int wc   = blockIdx.x;            // 0..1023
    const int w    = wc >> 1;
    const int dbase = (wc & 1) * 16;        // d-half of this CTA
    const int b  = w >> 8;
    const int wy = (w >> 4) & 15;
    const int wx = w & 15;
    const int wp   = t >> 5;                // warp 0..3 -> local d rows 4wp..4wp+3
    const int lane = t & 31;                // n and n+32

    uint4 pa[4];    // prefetched fp16 attn tile
    float4 pl[2];   // prefetched ll chunk

    {
        const uint4* ap = (const uint4*)&g_attnh[(w * 8 + 0) * 4096];
        #pragma unroll
        for (int i = 0; i < 4; ++i)
            pa[i] = ap[t + 128 * i];
        #pragma unroll
        for (int i = 0; i < 2; ++i) {
            int c  = t + 128 * i;            // 0..255
            int d  = c >> 4;                 // 0..15 local
            int m0 = (c & 15) * 4;
            int ch = b * DIMC + 0 * HD + dbase + d;
            pl[i] = *(const float4*)&g_ll[(ch * H2 + wy * 8 + (m0 >> 3)) * H2
                                          + wx * 8 + (m0 & 7)];
        }
    }

    for (int h = 0; h < HEADS; ++h) {
        __syncthreads();

        // ---- stage fp16 attn into padded [n][m] smem ----
        #pragma unroll
        for (int i = 0; i < 4; ++i) {
            int c = t + 128 * i;             // 0..511: n = c>>3, m0 = (c&7)*8
            *(uint4*)&attn_h[(c >> 3) * AROWH + (c & 7) * 8] = pa[i];
        }
        #pragma unroll
        for (int i = 0; i < 2; ++i) {
            int c = t + 128 * i;
            float4 v4 = pl[i];
            if (h > 0) {
                float4 o4 = *(const float4*)&o_s[c * 4];
                v4.x += o4.x; v4.y += o4.y; v4.z += o4.z; v4.w += o4.w;
                int d  = c >> 4;
                int m0 = (c & 15) * 4;
                __half2 r0 = __floats2half2_rn(fmaxf(o4.x, 0.f), fmaxf(o4.y, 0.f));
                __half2 r1 = __floats2half2_rn(fmaxf(o4.z, 0.f), fmaxf(o4.w, 0.f));
                uint2 rr = make_uint2(*(unsigned int*)&r0, *(unsigned int*)&r1);
                *(uint2*)&g_atth[((h - 1) * HD + dbase + d) * PIXTOT + w * 64 + m0] = rr;
            }
            *(float4*)&v_s[c * 4] = v4;
        }

        if (h < HEADS - 1) {
            const uint4* ap = (const uint4*)&g_attnh[(w * 8 + h + 1) * 4096];
            #pragma unroll
            for (int i = 0; i < 4; ++i)
                pa[i] = ap[t + 128 * i];
            #pragma unroll
            for (int i = 0; i < 2; ++i) {
                int c  = t + 128 * i;
                int d  = c >> 4;
                int m0 = (c & 15) * 4;
                int ch = b * DIMC + (h + 1) * HD + dbase + d;
                pl[i] = *(const float4*)&g_ll[(ch * H2 + wy * 8 + (m0 >> 3)) * H2
                                              + wx * 8 + (m0 & 7)];
            }
        }
        __syncthreads();

        // ---- out[d][n] = sum_m v[d][m] * attn[n][m], 8-m steps ----
        ull acc2[4][2];
        #pragma unroll
        for (int j = 0; j < 4; ++j) { acc2[j][0] = 0ull; acc2[j][1] = 0ull; }

        #pragma unroll
        for (int m = 0; m < 64; m += 8) {
            uint4 alh = *(const uint4*)&attn_h[lane * AROWH + m];
            uint4 ahh = *(const uint4*)&attn_h[(lane + 32) * AROWH + m];
            ull AL0 = h2_to_pack2(alh.x), AL1 = h2_to_pack2(alh.y);
            ull AL2 = h2_to_pack2(alh.z), AL3 = h2_to_pack2(alh.w);
            ull AH0 = h2_to_pack2(ahh.x), AH1 = h2_to_pack2(ahh.y);
            ull AH2 = h2_to_pack2(ahh.z), AH3 = h2_to_pack2(ahh.w);

            #pragma unroll
            for (int j = 0; j < 4; ++j) {
                ulonglong2 va = *(const ulonglong2*)&v_s[(4 * wp + j) * 64 + m];
                ulonglong2 vb = *(const ulonglong2*)&v_s[(4 * wp + j) * 64 + m + 4];
                ffma2(acc2[j][0], va.x, AL0); ffma2(acc2[j][0], va.y, AL1);
                ffma2(acc2[j][0], vb.x, AL2); ffma2(acc2[j][0], vb.y, AL3);
                ffma2(acc2[j][1], va.x, AH0); ffma2(acc2[j][1], va.y, AH1);
                ffma2(acc2[j][1], vb.x, AH2); ffma2(acc2[j][1], vb.y, AH3);
            }
        }
        #pragma unroll
        for (int j = 0; j < 4; ++j) {
            float2 u0 = unpack2(acc2[j][0]);
            float2 u1 = unpack2(acc2[j][1]);
            o_s[(4 * wp + j) * 64 + lane]      = u0.x + u0.y;
            o_s[(4 * wp + j) * 64 + lane + 32] = u1.x + u1.y;
        }
    }

    // ---- epilogue: relu-store head 7 output (fp16) ----
    __syncthreads();
    #pragma unroll
    for (int i = 0; i < 2; ++i) {
        int c  = t + 128 * i;
        int d  = c >> 4;
        int m0 = (c & 15) * 4;
        float4 o4 = *(const float4*)&o_s[c * 4];
        __half2 r0 = __floats2half2_rn(fmaxf(o4.x, 0.f), fmaxf(o4.y, 0.f));
        __half2 r1 = __floats2half2_rn(fmaxf(o4.z, 0.f), fmaxf(o4.w, 0.f));
        uint2 rr = make_uint2(*(unsigned int*)&r0, *(unsigned int*)&r1);
        *(uint2*)&g_atth[(7 * HD + dbase + d) * PIXTOT + w * 64 + m0] = rr;
    }
}

// ---------------- K3: proj GEMM  C[256,32768] = W[256,256] @ A + bias ------
// 128x128 tile, 8x8 micro-tile (packed f32x2), double-buffered smem.
// B read as fp16, converted to fp32 during smem staging.
__global__ __launch_bounds__(256) void proj_gemm(
    const float* __restrict__ Wm, const float* __restrict__ pb) {
    __shared__ float As[2][16 * PSROW];
    __shared__ float Bs[2][16 * PSROW];

    const int t  = threadIdx.x;
    const int n0 = blockIdx.x * 128;
    const int m0 = blockIdx.y * 128;
    const int tx = t & 15, ty = t >> 4;

    const int am = t >> 1;
    const int ak = (t & 1) * 8;
    const int bk = t >> 4;
    const int bn = (t & 15) * 8;

    ull acc2[8][4];
    #pragma unroll
    for (int i = 0; i < 8; ++i)
        #pragma unroll
        for (int j = 0; j < 4; ++j) acc2[i][j] = 0ull;

    float4 pa0 = *(const float4*)&Wm[(m0 + am) * 256 + ak];
    float4 pa1 = *(const float4*)&Wm[(m0 + am) * 256 + ak + 4];
    uint4  pbv = *(const uint4*)&g_atth[bk * PIXTOT + n0 + bn];   // 8 halfs

    for (int kt = 0; kt < 16; ++kt) {
        float* as = As[kt & 1];
        float* bs = Bs[kt & 1];
        as[(ak + 0) * PSROW + am] = pa0.x;
        as[(ak + 1) * PSROW + am] = pa0.y;
        as[(ak + 2) * PSROW + am] = pa0.z;
        as[(ak + 3) * PSROW + am] = pa0.w;
        as[(ak + 4) * PSROW + am] = pa1.x;
        as[(ak + 5) * PSROW + am] = pa1.y;
        as[(ak + 6) * PSROW + am] = pa1.z;
        as[(ak + 7) * PSROW + am] = pa1.w;
        {
            float2 b0 = __half22float2(*(__half2*)&pbv.x);
            float2 b1 = __half22float2(*(__half2*)&pbv.y);
            float2 b2 = __half22float2(*(__half2*)&pbv.z);
            float2 b3 = __half22float2(*(__half2*)&pbv.w);
            *(float4*)&bs[bk * PSROW + bn]     = make_float4(b0.x, b0.y, b1.x, b1.y);
            *(float4*)&bs[bk * PSROW + bn + 4] = make_float4(b2.x, b2.y, b3.x, b3.y);
        }

        if (kt < 15) {
            int k0 = (kt + 1) * 16;
            pa0 = *(const float4*)&Wm[(m0 + am) * 256 + k0 + ak];
            pa1 = *(const float4*)&Wm[(m0 + am) * 256 + k0 + ak + 4];
            pbv = *(const uint4*)&g_atth[(k0 + bk) * PIXTOT + n0 + bn];
        }
        __syncthreads();   // staging of buf[kt&1] complete

        #pragma unroll
        for (int k = 0; k < 16; ++k) {
            float4 a0 = *(const float4*)&as[k * PSROW + ty * 4];
            float4 a1 = *(const float4*)&as[k * PSROW + 64 + ty * 4];
            ulonglong2 b01 = *(const ulonglong2*)&bs[k * PSROW + tx * 4];
            ulonglong2 b23 = *(const ulonglong2*)&bs[k * PSROW + 64 + tx * 4];
            float av[8] = {a0.x, a0.y, a0.z, a0.w, a1.x, a1.y, a1.z, a1.w};
            #pragma unroll
            for (int i = 0; i < 8; ++i) {
                ull pav = pack2(av[i], av[i]);
                ffma2(acc2[i][0], pav, b01.x);
                ffma2(acc2[i][1], pav, b01.y);
                ffma2(acc2[i][2], pav, b23.x);
                ffma2(acc2[i][3], pav, b23.y);
            }
        }
        // no trailing barrier: next staging targets the other buffer
    }

    #pragma unroll
    for (int i = 0; i < 8; ++i) {
        int m = m0 + ((i < 4) ? (ty * 4 + i) : (64 + ty * 4 + i - 4));
        float bias = __ldg(&pb[m]);
        float* rp = &g_proj[m * PIXTOT + n0];
        float2 c0 = unpack2(acc2[i][0]);
        float2 c1 = unpack2(acc2[i][1]);
        float2 c2 = unpack2(acc2[i][2]);
        float2 c3 = unpack2(acc2[i][3]);
        float4 r0 = make_float4(c0.x + bias, c0.y + bias, c1.x + bias, c1.y + bias);
        float4 r1 = make_float4(c2.x + bias, c2.y + bias, c3.x + bias, c3.y + bias);
        *(float4*)&rp[tx * 4]      = r0;
        *(float4*)&rp[64 + tx * 4] = r1;
    }
}

// ---------------- K4: inverse wavelet (transposed depthwise 2x2) ------------
// 2 source pixels per thread: 4x LDG.64, 16 FFMA2, 2x STG.128
__global__ void iwt_kernel(const float* __restrict__ iwt, float* __restrict__ out) {
    int t  = threadIdx.x;          // 0..127
    int tx = t & 63;               // x-pair: source x = 2tx, 2tx+1
    int y  = 2 * blockIdx.x + (t >> 6);   // 0..127
    int bc = blockIdx.y;           // 0..511
    int b  = bc >> 8, c = bc & 255;

    int base = (bc * H2 + y) * H2 + 2 * tx;
    float2 lh = *(const float2*)&g_lh[base];
    float2 hl = *(const float2*)&g_hl[base];
    float2 hh = *(const float2*)&g_hh[base];

    int wy = y >> 3, pyy = y & 7, wx = (2 * tx) >> 3, pxx = (2 * tx) & 7;
    int wdx = (b * 16 + wy) * 16 + wx;
    float2 ll = *(const float2*)&g_proj[c * PIXTOT + wdx * 64 + pyy * 8 + pxx];

    const float4 f0 = __ldg((const float4*)&iwt[(4 * c + 0) * 4]);
    const float4 f1 = __ldg((const float4*)&iwt[(4 * c + 1) * 4]);
    const float4 f2 = __ldg((const float4*)&iwt[(4 * c + 2) * 4]);
    const float4 f3 = __ldg((const float4*)&iwt[(4 * c + 3) * 4]);

    // out row 2y:   (W.x, W.y) per source px; out row 2y+1: (W.z, W.w)
    ull t0a = 0, t0b = 0, t1a = 0, t1b = 0;   // a: src px0 (2 outs), b: src px1
    ull l0 = pack2(ll.x, ll.x), l1 = pack2(ll.y, ll.y);
    ull h0 = pack2(lh.x, lh.x), h1 = pack2(lh.y, lh.y);
    ull g0 = pack2(hl.x, hl.x), g1 = pack2(hl.y, hl.y);
    ull q0 = pack2(hh.x, hh.x), q1 = pack2(hh.y, hh.y);
    ull f0xy = pack2(f0.x, f0.y), f0zw = pack2(f0.z, f0.w);
    ull f1xy = pack2(f1.x, f1.y), f1zw = pack2(f1.z, f1.w);
    ull f2xy = pack2(f2.x, f2.y), f2zw = pack2(f2.z, f2.w);
    ull f3xy = pack2(f3.x, f3.y), f3zw = pack2(f3.z, f3.w);

    ffma2(t0a, l0, f0xy); ffma2(t0a, h0, f1xy); ffma2(t0a, g0, f2xy); ffma2(t0a, q0, f3xy);
    ffma2(t0b, l1, f0xy); ffma2(t0b, h1, f1xy); ffma2(t0b, g1, f2xy); ffma2(t0b, q1, f3xy);
    ffma2(t1a, l0, f0zw); ffma2(t1a, h0, f1zw); ffma2(t1a, g0, f2zw); ffma2(t1a, q0, f3zw);
    ffma2(t1b, l1, f0zw); ffma2(t1b, h1, f1zw); ffma2(t1b, g1, f2zw); ffma2(t1b, q1, f3zw);

    float2 u0a = unpack2(t0a), u0b = unpack2(t0b);
    float2 u1a = unpack2(t1a), u1b = unpack2(t1b);

    int ob = (bc * RESV + 2 * y) * RESV + 4 * tx;
    *(float4*)&out[ob]        = make_float4(u0a.x, u0a.y, u0b.x, u0b.y);
    *(float4*)&out[ob + RESV] = make_float4(u1a.x, u1a.y, u1b.x, u1b.y);
}

// ---------------- launch ----------------------------------------------------
extern "C" void kernel_launch(void* const* d_in, const int* in_sizes, int n_in,
                              void* d_out, int out_size) {
    const float* x    = (const float*)d_in[0];
    const float* wtf  = (const float*)d_in[1];
    const float* iwtf = (const float*)d_in[2];
    const float* dww  = (const float*)d_in[3];
    const float* dwb  = (const float*)d_in[4];
    const float* pw   = (const float*)d_in[5];
    const float* pb   = (const float*)d_in[6];
    const float* ab   = (const float*)d_in[7];
    const int*   bidx = (const int*)d_in[8];
    float* out = (float*)d_out;

    bias_kernel<<<128, 256>>>(ab, bidx);
    wt_kernel<<<dim3(64, 512), 128>>>(x, wtf);
    attn_mat_kernel<<<4096, 256>>>(dww, dwb);
    attn_av_kernel<<<1024, 128>>>();
    proj_gemm<<<dim3(256, 2), 256>>>(pw, pb);
    iwt_kernel<<<dim3(64, 512), 128>>>(iwtf, out);
}

// round 15
// speedup vs baseline: 1.1662x; 1.0496x over previous
#include <cuda_runtime.h>
#include <cuda_fp16.h>

#define DIMC 256
#define RESV 256
#define H2 128
#define HEADS 8
#define HD 32
#define NPIX 64
#define NWIN 512
#define PIXTOT (NWIN * NPIX)   // 32768
#define ATTN_SCALE 0.17677669529663687f
#define SROW 68                // padded smem row stride (floats)
#define AROWH 72               // attn_av padded attn row stride (halfs, 144B rows)
#define PSROW 132              // proj smem row stride (floats), 128-wide tiles

typedef unsigned long long ull;

// ---- packed fp32x2 helpers (FFMA2 — only reachable via PTX fma.rn.f32x2) ----
__device__ __forceinline__ void ffma2(ull& d, ull a, ull b) {
    asm("fma.rn.f32x2 %0, %1, %2, %0;" : "+l"(d) : "l"(a), "l"(b));
}
__device__ __forceinline__ ull pack2(float lo, float hi) {
    ull r; asm("mov.b64 %0, {%1, %2};" : "=l"(r) : "f"(lo), "f"(hi)); return r;
}
__device__ __forceinline__ float2 unpack2(ull v) {
    float2 r; asm("mov.b64 {%0, %1}, %2;" : "=f"(r.x), "=f"(r.y) : "l"(v)); return r;
}
__device__ __forceinline__ ull h2_to_pack2(unsigned int h2) {
    float2 f = __half22float2(*(__half2*)&h2);
    return pack2(f.x, f.y);
}
__device__ __forceinline__ unsigned int f2_to_h2(float lo, float hi) {
    __half2 h = __floats2half2_rn(lo, hi);
    return *(unsigned int*)&h;
}

// ---------------- scratch (static device allocations; no cudaMalloc) -------
__device__ float  g_ll[2 * DIMC * H2 * H2];    // ll stays fp32 (seeds the head chain)
__device__ __half g_lh16[2 * DIMC * H2 * H2];  // fp16 bands
__device__ __half g_hl16[2 * DIMC * H2 * H2];
__device__ __half g_hh16[2 * DIMC * H2 * H2];
__device__ __half g_attnh[NWIN * HEADS * NPIX * NPIX]; // softmax'd attn fp16, [wh][n][m]
__device__ __half g_atth[DIMC * PIXTOT];  // relu(attention out) fp16, [c][pix]
__device__ float g_proj[DIMC * PIXTOT];   // proj out fp32, [o][pix]
__device__ float g_bias[HEADS * NPIX * NPIX];

// ---------------- K0: expand attention bias table ---------------------------
__global__ void bias_kernel(const float* __restrict__ ab, const int* __restrict__ bidx) {
    int i = blockIdx.x * 256 + threadIdx.x;     // 32768 total
    int h = i >> 12;
    g_bias[i] = ab[h * 64 + bidx[i & 4095]];
}

// ---------------- K1: wavelet transform (depthwise 2x2 stride 2) -----------
// 2 output pixels per thread. ll stored fp32, lh/hl/hh stored fp16.
__global__ void wt_kernel(const float* __restrict__ x, const float* __restrict__ wt) {
    int t  = threadIdx.x;          // 0..127
    int tx = t & 63;               // x-pair index: outputs x = 2tx, 2tx+1
    int y  = 2 * blockIdx.x + (t >> 6);   // 0..127
    int bc = blockIdx.y;           // 0..511
    int c  = bc & 255;

    const float4 f0 = __ldg((const float4*)&wt[(4 * c + 0) * 4]);
    const float4 f1 = __ldg((const float4*)&wt[(4 * c + 1) * 4]);
    const float4 f2 = __ldg((const float4*)&wt[(4 * c + 2) * 4]);
    const float4 f3 = __ldg((const float4*)&wt[(4 * c + 3) * 4]);

    int ib = (bc * RESV + 2 * y) * RESV + 4 * tx;
    float4 p0 = *(const float4*)&x[ib];
    float4 p1 = *(const float4*)&x[ib + RESV];

    ull A0 = pack2(p0.x, p0.z), A1 = pack2(p0.y, p0.w);
    ull A2 = pack2(p1.x, p1.z), A3 = pack2(p1.y, p1.w);

    ull r0 = 0, r1 = 0, r2 = 0, r3 = 0;
    ffma2(r0, A0, pack2(f0.x, f0.x)); ffma2(r0, A1, pack2(f0.y, f0.y));
    ffma2(r0, A2, pack2(f0.z, f0.z)); ffma2(r0, A3, pack2(f0.w, f0.w));
    ffma2(r1, A0, pack2(f1.x, f1.x)); ffma2(r1, A1, pack2(f1.y, f1.y));
    ffma2(r1, A2, pack2(f1.z, f1.z)); ffma2(r1, A3, pack2(f1.w, f1.w));
    ffma2(r2, A0, pack2(f2.x, f2.x)); ffma2(r2, A1, pack2(f2.y, f2.y));
    ffma2(r2, A2, pack2(f2.z, f2.z)); ffma2(r2, A3, pack2(f2.w, f2.w));
    ffma2(r3, A0, pack2(f3.x, f3.x)); ffma2(r3, A1, pack2(f3.y, f3.y));
    ffma2(r3, A2, pack2(f3.z, f3.z)); ffma2(r3, A3, pack2(f3.w, f3.w));

    int ob = (bc * H2 + y) * H2 + 2 * tx;
    *(float2*)&g_ll[ob] = unpack2(r0);
    float2 u1 = unpack2(r1), u2 = unpack2(r2), u3 = unpack2(r3);
    *(unsigned int*)&g_lh16[ob] = f2_to_h2(u1.x, u1.y);
    *(unsigned int*)&g_hl16[ob] = f2_to_h2(u2.x, u2.y);
    *(unsigned int*)&g_hh16[ob] = f2_to_h2(u3.x, u3.y);
}

// ---------------- K2a: attention matrices (all heads parallel) --------------
// One CTA per (window, head). lh/hl loaded fp16, converted to fp32 in smem.
// Output stored [wh][n][m] as fp16 — 2x STG.128.
__global__ __launch_bounds__(256) void attn_mat_kernel(
    const float* __restrict__ dww, const float* __restrict__ dwb) {
    __shared__ float lh_s[HD * SROW];
    __shared__ float k_s[HD * SROW];
    __shared__ float q_s[HD * SROW];
    __shared__ float w_s[HD * 25];

    const int t  = threadIdx.x;
    const int wh = blockIdx.x;           // 0..4095
    const int w  = wh >> 3;
    const int h  = wh & 7;
    const int b  = w >> 8;
    const int wy = (w >> 4) & 15;
    const int wx = w & 15;
    const int dl = t >> 3;               // 0..31
    const int py = t & 7;                // 0..7

    {
        int ch   = b * DIMC + h * HD + dl;
        int base = (ch * H2 + wy * 8 + py) * H2 + wx * 8;
        int o0   = dl * SROW + py * 8;
        uint4 lv = *(const uint4*)&g_lh16[base];   // 8 halfs
        uint4 kv = *(const uint4*)&g_hl16[base];
        float2 l0 = __half22float2(*(__half2*)&lv.x);
        float2 l1 = __half22float2(*(__half2*)&lv.y);
        float2 l2 = __half22float2(*(__half2*)&lv.z);
        float2 l3 = __half22float2(*(__half2*)&lv.w);
        float2 k0 = __half22float2(*(__half2*)&kv.x);
        float2 k1 = __half22float2(*(__half2*)&kv.y);
        float2 k2 = __half22float2(*(__half2*)&kv.z);
        float2 k3 = __half22float2(*(__half2*)&kv.w);
        *(float4*)&lh_s[o0]     = make_float4(l0.x, l0.y, l1.x, l1.y);
        *(float4*)&lh_s[o0 + 4] = make_float4(l2.x, l2.y, l3.x, l3.y);
        *(float4*)&k_s[o0]      = make_float4(k0.x, k0.y, k1.x, k1.y);
        *(float4*)&k_s[o0 + 4]  = make_float4(k2.x, k2.y, k3.x, k3.y);
    }
    for (int i = t; i < HD * 25; i += 256) w_s[i] = dww[h * HD * 25 + i];
    __syncthreads();

    // ---- q = depthwise 5x5 conv on lh ----
    {
        float accq[8];
        float bias0 = __ldg(&dwb[h * HD + dl]);
        #pragma unroll
        for (int px = 0; px < 8; ++px) accq[px] = bias0;
        #pragma unroll
        for (int u = 0; u < 5; ++u) {
            int yy = py + u - 2;
            if (yy >= 0 && yy < 8) {
                float4 r0 = *(const float4*)&lh_s[dl * SROW + yy * 8];
                float4 r1 = *(const float4*)&lh_s[dl * SROW + yy * 8 + 4];
                float r[8] = {r0.x, r0.y, r0.z, r0.w, r1.x, r1.y, r1.z, r1.w};
                #pragma unroll
                for (int v = 0; v < 5; ++v) {
                    float wv = w_s[dl * 25 + u * 5 + v];
                    #pragma unroll
                    for (int px = 0; px < 8; ++px) {
                        int xx = px + v - 2;
                        if (xx >= 0 && xx < 8)
                            accq[px] += r[xx] * wv;
                    }
                }
            }
        }
        #pragma unroll
        for (int px = 0; px < 8; ++px) q_s[dl * SROW + py * 8 + px] = accq[px];
    }
    __syncthreads();

    // ---- attn = softmax(q.k * scale + bias), packed f32x2 QK ----
    {
        int n  = t >> 2;
        int mq = t & 3;
        ull acc2[8];
        #pragma unroll
        for (int i = 0; i < 8; ++i) acc2[i] = 0ull;

        #pragma unroll 4
        for (int d2 = 0; d2 < HD; ++d2) {
            float qd = q_s[d2 * SROW + n];
            ull pq = pack2(qd, qd);
            const float* kp = &k_s[d2 * SROW + mq * 16];
            ulonglong2 k01 = *(const ulonglong2*)(kp);
            ulonglong2 k23 = *(const ulonglong2*)(kp + 4);
            ulonglong2 k45 = *(const ulonglong2*)(kp + 8);
            ulonglong2 k67 = *(const ulonglong2*)(kp + 12);
            ffma2(acc2[0], pq, k01.x);
            ffma2(acc2[1], pq, k01.y);
            ffma2(acc2[2], pq, k23.x);
            ffma2(acc2[3], pq, k23.y);
            ffma2(acc2[4], pq, k45.x);
            ffma2(acc2[5], pq, k45.y);
            ffma2(acc2[6], pq, k67.x);
            ffma2(acc2[7], pq, k67.y);
        }

        float acc[16];
        #pragma unroll
        for (int i = 0; i < 8; ++i) {
            float2 u = unpack2(acc2[i]);
            acc[2 * i]     = u.x;
            acc[2 * i + 1] = u.y;
        }

        const float* bptr = &g_bias[h * 4096 + n * 64 + mq * 16];
        float mx = -1e30f;
        #pragma unroll
        for (int mi = 0; mi < 16; ++mi) {
            acc[mi] = acc[mi] * ATTN_SCALE + __ldg(&bptr[mi]);
            mx = fmaxf(mx, acc[mi]);
        }
        mx = fmaxf(mx, __shfl_xor_sync(0xffffffffu, mx, 1));
        mx = fmaxf(mx, __shfl_xor_sync(0xffffffffu, mx, 2));
        float s = 0.f;
        #pragma unroll
        for (int mi = 0; mi < 16; ++mi) {
            float e = __expf(acc[mi] - mx);
            acc[mi] = e;
            s += e;
        }
        s += __shfl_xor_sync(0xffffffffu, s, 1);
        s += __shfl_xor_sync(0xffffffffu, s, 2);
        float inv = 1.f / s;

        // ---- fp16 [n][m] layout: 16 halfs contiguous -> 2x STG.128 ----
        __half2 hb[8];
        #pragma unroll
        for (int g2 = 0; g2 < 8; ++g2)
            hb[g2] = __floats2half2_rn(acc[2 * g2] * inv, acc[2 * g2 + 1] * inv);
        __half* op = &g_attnh[wh * 4096 + n * 64 + mq * 16];
        *(uint4*)op       = *(uint4*)&hb[0];
        *(uint4*)(op + 8) = *(uint4*)&hb[4];
    }
}

// ---------------- K2b: sequential AV chain, 2 CTAs per window (d-split) ----
// fp16 attn tile ([n][m], AROWH=72), fp16 relu output. ll read fp32.
__global__ __launch_bounds__(128) void attn_av_kernel() {
    __shared__ float v_s[16 * NPIX];          // 4KB
    __shared__ float o_s[16 * NPIX];          // 4KB
    __shared__ __half attn_h[NPIX * AROWH];   // 9KB, fp16 [n][m] padded

    const int t    = threadIdx.x;           // 0..127
    const int wc   = blockIdx.x;            // 0..1023
    const int w    = wc >> 1;
    const int dbase = (wc & 1) * 16;        // d-half of this CTA
    const int b  = w >> 8;
    const int wy = (w >> 4) & 15;
    const int wx = w & 15;
    const int wp   = t >> 5;                // warp 0..3 -> local d rows 4wp..4wp+3
    const int lane = t & 31;                // n and n+32

    uint4 pa[4];    // prefetched fp16 attn tile
    float4 pl[2];   // prefetched ll chunk

    {
        const uint4* ap = (const uint4*)&g_attnh[(w * 8 + 0) * 4096];
        #pragma unroll
        for (int i = 0; i < 4; ++i)
            pa[i] = ap[t + 128 * i];
        #pragma unroll
        for (int i = 0; i < 2; ++i) {
            int c  = t + 128 * i;            // 0..255
            int d  = c >> 4;                 // 0..15 local
            int m0 = (c & 15) * 4;
            int ch = b * DIMC + 0 * HD + dbase + d;
            pl[i] = *(const float4*)&g_ll[(ch * H2 + wy * 8 + (m0 >> 3)) * H2
                                          + wx * 8 + (m0 & 7)];
        }
    }

    for (int h = 0; h < HEADS; ++h) {
        __syncthreads();

        // ---- stage fp16 attn into padded [n][m] smem ----
        #pragma unroll
        for (int i = 0; i < 4; ++i) {
            int c = t + 128 * i;             // 0..511: n = c>>3, m0 = (c&7)*8
            *(uint4*)&attn_h[(c >> 3) * AROWH + (c & 7) * 8] = pa[i];
        }
        #pragma unroll
        for (int i = 0; i < 2; ++i) {
            int c = t + 128 * i;
            float4 v4 = pl[i];
            if (h > 0) {
                float4 o4 = *(const float4*)&o_s[c * 4];
                v4.x += o4.x; v4.y += o4.y; v4.z += o4.z; v4.w += o4.w;
                int d  = c >> 4;
                int m0 = (c & 15) * 4;
                uint2 rr = make_uint2(f2_to_h2(fmaxf(o4.x, 0.f), fmaxf(o4.y, 0.f)),
                                      f2_to_h2(fmaxf(o4.z, 0.f), fmaxf(o4.w, 0.f)));
                *(uint2*)&g_atth[((h - 1) * HD + dbase + d) * PIXTOT + w * 64 + m0] = rr;
            }
            *(float4*)&v_s[c * 4] = v4;
        }

        if (h < HEADS - 1) {
            const uint4* ap = (const uint4*)&g_attnh[(w * 8 + h + 1) * 4096];
            #pragma unroll
            for (int i = 0; i < 4; ++i)
                pa[i] = ap[t + 128 * i];
            #pragma unroll
            for (int i = 0; i < 2; ++i) {
                int c  = t + 128 * i;
                int d  = c >> 4;
                int m0 = (c & 15) * 4;
                int ch = b * DIMC + (h + 1) * HD + dbase + d;
                pl[i] = *(const float4*)&g_ll[(ch * H2 + wy * 8 + (m0 >> 3)) * H2
                                              + wx * 8 + (m0 & 7)];
            }
        }
        __syncthreads();

        // ---- out[d][n] = sum_m v[d][m] * attn[n][m], 8-m steps ----
        ull acc2[4][2];
        #pragma unroll
        for (int j = 0; j < 4; ++j) { acc2[j][0] = 0ull; acc2[j][1] = 0ull; }

        #pragma unroll
        for (int m = 0; m < 64; m += 8) {
            uint4 alh = *(const uint4*)&attn_h[lane * AROWH + m];
            uint4 ahh = *(const uint4*)&attn_h[(lane + 32) * AROWH + m];
            ull AL0 = h2_to_pack2(alh.x), AL1 = h2_to_pack2(alh.y);
            ull AL2 = h2_to_pack2(alh.z), AL3 = h2_to_pack2(alh.w);
            ull AH0 = h2_to_pack2(ahh.x), AH1 = h2_to_pack2(ahh.y);
            ull AH2 = h2_to_pack2(ahh.z), AH3 = h2_to_pack2(ahh.w);

            #pragma unroll
            for (int j = 0; j < 4; ++j) {
                ulonglong2 va = *(const ulonglong2*)&v_s[(4 * wp + j) * 64 + m];
                ulonglong2 vb = *(const ulonglong2*)&v_s[(4 * wp + j) * 64 + m + 4];
                ffma2(acc2[j][0], va.x, AL0); ffma2(acc2[j][0], va.y, AL1);
                ffma2(acc2[j][0], vb.x, AL2); ffma2(acc2[j][0], vb.y, AL3);
                ffma2(acc2[j][1], va.x, AH0); ffma2(acc2[j][1], va.y, AH1);
                ffma2(acc2[j][1], vb.x, AH2); ffma2(acc2[j][1], vb.y, AH3);
            }
        }
        #pragma unroll
        for (int j = 0; j < 4; ++j) {
            float2 u0 = unpack2(acc2[j][0]);
            float2 u1 = unpack2(acc2[j][1]);
            o_s[(4 * wp + j) * 64 + lane]      = u0.x + u0.y;
            o_s[(4 * wp + j) * 64 + lane + 32] = u1.x + u1.y;
        }
    }

    // ---- epilogue: relu-store head 7 output (fp16) ----
    __syncthreads();
    #pragma unroll
    for (int i = 0; i < 2; ++i) {
        int c  = t + 128 * i;
        int d  = c >> 4;
        int m0 = (c & 15) * 4;
        float4 o4 = *(const float4*)&o_s[c * 4];
        uint2 rr = make_uint2(f2_to_h2(fmaxf(o4.x, 0.f), fmaxf(o4.y, 0.f)),
                              f2_to_h2(fmaxf(o4.z, 0.f), fmaxf(o4.w, 0.f)));
        *(uint2*)&g_atth[(7 * HD + dbase + d) * PIXTOT + w * 64 + m0] = rr;
    }
}

// ---------------- K3: proj GEMM  C[256,32768] = W[256,256] @ A + bias ------
// 128x128 tile, 8x8 micro-tile (packed f32x2), double-buffered smem.
// B read as fp16, converted to fp32 during smem staging.
__global__ __launch_bounds__(256) void proj_gemm(
    const float* __restrict__ Wm, const float* __restrict__ pb) {
    __shared__ float As[2][16 * PSROW];
    __shared__ float Bs[2][16 * PSROW];

    const int t  = threadIdx.x;
    const int n0 = blockIdx.x * 128;
    const int m0 = blockIdx.y * 128;
    const int tx = t & 15, ty = t >> 4;

    const int am = t >> 1;
    const int ak = (t & 1) * 8;
    const int bk = t >> 4;
    const int bn = (t & 15) * 8;

    ull acc2[8][4];
    #pragma unroll
    for (int i = 0; i < 8; ++i)
        #pragma unroll
        for (int j = 0; j < 4; ++j) acc2[i][j] = 0ull;

    float4 pa0 = *(const float4*)&Wm[(m0 + am) * 256 + ak];
    float4 pa1 = *(const float4*)&Wm[(m0 + am) * 256 + ak + 4];
    uint4  pbv = *(const uint4*)&g_atth[bk * PIXTOT + n0 + bn];   // 8 halfs

    for (int kt = 0; kt < 16; ++kt) {
        float* as = As[kt & 1];
        float* bs = Bs[kt & 1];
        as[(ak + 0) * PSROW + am] = pa0.x;
        as[(ak + 1) * PSROW + am] = pa0.y;
        as[(ak + 2) * PSROW + am] = pa0.z;
        as[(ak + 3) * PSROW + am] = pa0.w;
        as[(ak + 4) * PSROW + am] = pa1.x;
        as[(ak + 5) * PSROW + am] = pa1.y;
        as[(ak + 6) * PSROW + am] = pa1.z;
        as[(ak + 7) * PSROW + am] = pa1.w;
        {
            float2 b0 = __half22float2(*(__half2*)&pbv.x);
            float2 b1 = __half22float2(*(__half2*)&pbv.y);
            float2 b2 = __half22float2(*(__half2*)&pbv.z);
            float2 b3 = __half22float2(*(__half2*)&pbv.w);
            *(float4*)&bs[bk * PSROW + bn]     = make_float4(b0.x, b0.y, b1.x, b1.y);
            *(float4*)&bs[bk * PSROW + bn + 4] = make_float4(b2.x, b2.y, b3.x, b3.y);
        }

        if (kt < 15) {
            int k0 = (kt + 1) * 16;
            pa0 = *(const float4*)&Wm[(m0 + am) * 256 + k0 + ak];
            pa1 = *(const float4*)&Wm[(m0 + am) * 256 + k0 + ak + 4];
            pbv = *(const uint4*)&g_atth[(k0 + bk) * PIXTOT + n0 + bn];
        }
        __syncthreads();   // staging of buf[kt&1] complete

        #pragma unroll
        for (int k = 0; k < 16; ++k) {
            float4 a0 = *(const float4*)&as[k * PSROW + ty * 4];
            float4 a1 = *(const float4*)&as[k * PSROW + 64 + ty * 4];
            ulonglong2 b01 = *(const ulonglong2*)&bs[k * PSROW + tx * 4];
            ulonglong2 b23 = *(const ulonglong2*)&bs[k * PSROW + 64 + tx * 4];
            float av[8] = {a0.x, a0.y, a0.z, a0.w, a1.x, a1.y, a1.z, a1.w};
            #pragma unroll
            for (int i = 0; i < 8; ++i) {
                ull pav = pack2(av[i], av[i]);
                ffma2(acc2[i][0], pav, b01.x);
                ffma2(acc2[i][1], pav, b01.y);
                ffma2(acc2[i][2], pav, b23.x);
                ffma2(acc2[i][3], pav, b23.y);
            }
        }
        // no trailing barrier: next staging targets the other buffer
    }

    #pragma unroll
    for (int i = 0; i < 8; ++i) {
        int m = m0 + ((i < 4) ? (ty * 4 + i) : (64 + ty * 4 + i - 4));
        float bias = __ldg(&pb[m]);
        float* rp = &g_proj[m * PIXTOT + n0];
        float2 c0 = unpack2(acc2[i][0]);
        float2 c1 = unpack2(acc2[i][1]);
        float2 c2 = unpack2(acc2[i][2]);
        float2 c3 = unpack2(acc2[i][3]);
        float4 r0 = make_float4(c0.x + bias, c0.y + bias, c1.x + bias, c1.y + bias);
        float4 r1 = make_float4(c2.x + bias, c2.y + bias, c3.x + bias, c3.y + bias);
        *(float4*)&rp[tx * 4]      = r0;
        *(float4*)&rp[64 + tx * 4] = r1;
    }
}

// ---------------- K4: inverse wavelet (transposed depthwise 2x2) ------------
// 2 source pixels per thread. lh/hl/hh read fp16, ll from fp32 g_proj.
__global__ void iwt_kernel(const float* __restrict__ iwt, float* __restrict__ out) {
    int t  = threadIdx.x;          // 0..127
    int tx = t & 63;               // x-pair: source x = 2tx, 2tx+1
    int y  = 2 * blockIdx.x + (t >> 6);   // 0..127
    int bc = blockIdx.y;           // 0..511
    int b  = bc >> 8, c = bc & 255;

    int base = (bc * H2 + y) * H2 + 2 * tx;
    unsigned int lhb = *(const unsigned int*)&g_lh16[base];
    unsigned int hlb = *(const unsigned int*)&g_hl16[base];
    unsigned int hhb = *(const unsigned int*)&g_hh16[base];
    float2 lh = __half22float2(*(__half2*)&lhb);
    float2 hl = __half22float2(*(__half2*)&hlb);
    float2 hh = __half22float2(*(__half2*)&hhb);

    int wy = y >> 3, pyy = y & 7, wx = (2 * tx) >> 3, pxx = (2 * tx) & 7;
    int wdx = (b * 16 + wy) * 16 + wx;
    float2 ll = *(const float2*)&g_proj[c * PIXTOT + wdx * 64 + pyy * 8 + pxx];

    const float4 f0 = __ldg((const float4*)&iwt[(4 * c + 0) * 4]);
    const float4 f1 = __ldg((const float4*)&iwt[(4 * c + 1) * 4]);
    const float4 f2 = __ldg((const float4*)&iwt[(4 * c + 2) * 4]);
    const float4 f3 = __ldg((const float4*)&iwt[(4 * c + 3) * 4]);

    ull t0a = 0, t0b = 0, t1a = 0, t1b = 0;
    ull l0 = pack2(ll.x, ll.x), l1 = pack2(ll.y, ll.y);
    ull h0 = pack2(lh.x, lh.x), h1 = pack2(lh.y, lh.y);
    ull g0 = pack2(hl.x, hl.x), g1 = pack2(hl.y, hl.y);
    ull q0 = pack2(hh.x, hh.x), q1 = pack2(hh.y, hh.y);
    ull f0xy = pack2(f0.x, f0.y), f0zw = pack2(f0.z, f0.w);
    ull f1xy = pack2(f1.x, f1.y), f1zw = pack2(f1.z, f1.w);
    ull f2xy = pack2(f2.x, f2.y), f2zw = pack2(f2.z, f2.w);
    ull f3xy = pack2(f3.x, f3.y), f3zw = pack2(f3.z, f3.w);

    ffma2(t0a, l0, f0xy); ffma2(t0a, h0, f1xy); ffma2(t0a, g0, f2xy); ffma2(t0a, q0, f3xy);
    ffma2(t0b, l1, f0xy); ffma2(t0b, h1, f1xy); ffma2(t0b, g1, f2xy); ffma2(t0b, q1, f3xy);
    ffma2(t1a, l0, f0zw); ffma2(t1a, h0, f1zw); ffma2(t1a, g0, f2zw); ffma2(t1a, q0, f3zw);
    ffma2(t1b, l1, f0zw); ffma2(t1b, h1, f1zw); ffma2(t1b, g1, f2zw); ffma2(t1b, q1, f3zw);

    float2 u0a = unpack2(t0a), u0b = unpack2(t0b);
    float2 u1a = unpack2(t1a), u1b = unpack2(t1b);

    int ob = (bc * RESV + 2 * y) * RESV + 4 * tx;
    *(float4*)&out[ob]        = make_float4(u0a.x, u0a.y, u0b.x, u0b.y);
    *(float4*)&out[ob + RESV] = make_float4(u1a.x, u1a.y, u1b.x, u1b.y);
}

// ---------------- launch ----------------------------------------------------
extern "C" void kernel_launch(void* const* d_in, const int* in_sizes, int n_in,
                              void* d_out, int out_size) {
    const float* x    = (const float*)d_in[0];
    const float* wtf  = (const float*)d_in[1];
    const float* iwtf = (const float*)d_in[2];
    const float* dww  = (const float*)d_in[3];
    const float* dwb  = (const float*)d_in[4];
    const float* pw   = (const float*)d_in[5];
    const float* pb   = (const float*)d_in[6];
    const float* ab   = (const float*)d_in[7];
    const int*   bidx = (const int*)d_in[8];
    float* out = (float*)d_out;

    bias_kernel<<<128, 256>>>(ab, bidx);
    wt_kernel<<<dim3(64, 512), 128>>>(x, wtf);
    attn_mat_kernel<<<4096, 256>>>(dww, dwb);
    attn_av_kernel<<<1024, 128>>>();
    proj_gemm<<<dim3(256, 2), 256>>>(pw, pb);
    iwt_kernel<<<dim3(64, 512), 128>>>(iwtf, out);
}